// round 4
// baseline (speedup 1.0000x reference)
#include <cuda_runtime.h>
#include <cuda_bf16.h>
#include <math.h>
#include <stdint.h>

// ---------------- problem sizes ----------------
#define NMS_N   256
#define HW      16384          // 128*128
#define WORDS   512            // 16384/32
#define NB      64             // batch for CRF
#define NPIX    (NB*HW)        // 1,048,576

// ---------------- smem layout for persistent CRF ----------------
#define W136    136                         // padded row stride (4 left pad, 4 right pad)
#define PLW     (65*W136)                   // weight plane: 1 top-halo row + 64 rows
#define PLS     (66*W136)                   // state plane: top halo + 64 + bottom halo
#define SMF     (4*PLW + 2*PLS)             // 53312 floats = 213248 bytes

// ---------------- device scratch (static, no allocation) ----------------
__device__ unsigned int g_packedT[WORDS * NMS_N];
__device__ float        g_sums[NMS_N];
__device__ float        g_dmat[NMS_N * NMS_N];
__device__ float        g_comp[NMS_N];

__device__ __align__(16) float g_wE [NPIX];
__device__ __align__(16) float g_wS [NPIX];
__device__ __align__(16) float g_wSE[NPIX];
__device__ __align__(16) float g_wSW[NPIX];
__device__ int g_cnt[NB];

// ================= helpers =================

__device__ __forceinline__ void cluster_sync_() {
    asm volatile("barrier.cluster.arrive.aligned;" ::: "memory");
    asm volatile("barrier.cluster.wait.aligned;" ::: "memory");
}

__device__ __forceinline__ void st_peer_f32(uint32_t local_addr, uint32_t peer_rank, float v) {
    uint32_t rem;
    asm volatile("mapa.shared::cluster.u32 %0, %1, %2;"
                 : "=r"(rem) : "r"(local_addr), "r"(peer_rank));
    asm volatile("st.shared::cluster.f32 [%0], %1;" :: "r"(rem), "f"(v) : "memory");
}

// ================= NMS =================

__global__ void pack_kernel(const float* __restrict__ seg) {
    int m   = blockIdx.x;
    int tid = threadIdx.x;         // 512 threads
    int warp = tid >> 5, lane = tid & 31;
    if (blockIdx.x == 0 && tid < NB) g_cnt[tid] = 0;
    int cnt = 0;
    for (int w = warp; w < WORDS; w += 16) {
        float v = seg[(size_t)m * HW + w * 32 + lane];
        unsigned bal = __ballot_sync(0xffffffffu, v != 0.0f);
        if (lane == 0) {
            g_packedT[w * NMS_N + m] = bal;
            cnt += __popc(bal);
        }
    }
    __shared__ int scnt[16];
    if (lane == 0) scnt[warp] = cnt;
    __syncthreads();
    if (tid == 0) {
        int t = 0;
        for (int i = 0; i < 16; ++i) t += scnt[i];
        g_sums[m] = (float)t;
    }
}

__global__ void nms_iou_kernel(const int* __restrict__ labels) {
    int j = blockIdx.x;
    int i = threadIdx.x;
    __shared__ unsigned int smj[WORDS];
    for (int w = i; w < WORDS; w += NMS_N) smj[w] = g_packedT[w * NMS_N + j];
    __syncthreads();

    float d = 0.0f;
    if (i < j && labels[i] == labels[j]) {
        int inter = 0;
        #pragma unroll 4
        for (int w = 0; w < WORDS; ++w)
            inter += __popc(g_packedT[w * NMS_N + i] & smj[w]);
        float fi  = (float)inter;
        float uni = g_sums[j] + g_sums[i] - fi;
        d = fi / uni;
    }
    g_dmat[j * NMS_N + i] = d;

    __shared__ float red[NMS_N];
    red[i] = d;
    __syncthreads();
    for (int s = NMS_N / 2; s > 0; s >>= 1) {
        if (i < s) red[i] = fmaxf(red[i], red[i + s]);
        __syncthreads();
    }
    if (i == 0) g_comp[j] = red[0];
}

__global__ void nms_coef_kernel(const float* __restrict__ cate_scores,
                                float* __restrict__ out_scores) {
    int j = blockIdx.x;
    int i = threadIdx.x;
    float d  = g_dmat[j * NMS_N + i];
    float ci = g_comp[i];
    float v  = expf(-2.0f * d * d) / expf(-2.0f * ci * ci);
    __shared__ float red[NMS_N];
    red[i] = v;
    __syncthreads();
    for (int s = NMS_N / 2; s > 0; s >>= 1) {
        if (i < s) red[i] = fminf(red[i], red[i + s]);
        __syncthreads();
    }
    if (i == 0) out_scores[j] = cate_scores[j] * red[0];
}

// ================= CRF weights (exact, unchanged math) =================

__global__ void crf_weights_kernel(const float* __restrict__ fm) {
    int idx = blockIdx.x * blockDim.x + threadIdx.x;
    if (idx >= NPIX) return;
    int b   = idx >> 14;
    int pix = idx & (HW - 1);
    int h   = pix >> 7, w = pix & 127;

    const float* fb = fm + (size_t)b * 3 * HW;
    float c0 = fb[pix] + 10.0f;
    float c1 = fb[HW + pix] + 10.0f;
    float c2 = fb[2 * HW + pix] + 10.0f;

    const int   di[4]  = {0, 1, 1, 1};
    const int   dj[4]  = {1, 0, 1, -1};
    const float sp[4]  = {1.0f / 1800.0f, 1.0f / 1800.0f, 2.0f / 1800.0f, 2.0f / 1800.0f};
    float wv[4];
    #pragma unroll
    for (int k = 0; k < 4; ++k) {
        int hh = h + di[k], ww = w + dj[k];
        float v = 0.0f;
        if (hh < 128 && ww >= 0 && ww < 128) {
            int np = hh * 128 + ww;
            float d0 = (fb[np] + 10.0f) - c0;
            float d1 = (fb[HW + np] + 10.0f) - c1;
            float d2 = (fb[2 * HW + np] + 10.0f) - c2;
            float ss = d0 * d0 + d1 * d1 + d2 * d2;
            v = 3.0f * expf(-ss * 2.0f - sp[k]);
        }
        wv[k] = v;
    }
    g_wE [idx] = wv[0];
    g_wS [idx] = wv[1];
    g_wSE[idx] = wv[2];
    g_wSW[idx] = wv[3];
}

// ================= persistent CRF: 10 iterations in one kernel =================

__device__ __forceinline__ void group4(const float* __restrict__ A,
                                       const float* __restrict__ wEp,
                                       const float* __restrict__ wSp,
                                       const float* __restrict__ wSEp,
                                       const float* __restrict__ wSWp,
                                       int ro, float m[4]) {
    const float* Ar = A + ro;
    float4 cu = *(const float4*)(Ar - W136);
    float4 cm = *(const float4*)(Ar);
    float4 cd = *(const float4*)(Ar + W136);
    float lu = Ar[-W136 - 1], ru = Ar[-W136 + 4];
    float lm = Ar[-1],        rm = Ar[4];
    float ldv = Ar[W136 - 1], rd = Ar[W136 + 4];

    float tw[6] = {lu,  cu.x, cu.y, cu.z, cu.w, ru};
    float mw[6] = {lm,  cm.x, cm.y, cm.z, cm.w, rm};
    float bw[6] = {ldv, cd.x, cd.y, cd.z, cd.w, rd};

    const float* eR = wEp + ro;
    float4 eO = *(const float4*)eR;  float eWl = eR[-1];
    const float* sR = wSp + ro;
    float4 sO = *(const float4*)sR;  float4 sN = *(const float4*)(sR - W136);
    const float* seR = wSEp + ro;
    float4 seO = *(const float4*)seR; float4 seN = *(const float4*)(seR - W136);
    float seNl = seR[-W136 - 1];
    const float* swR = wSWp + ro;
    float4 swO = *(const float4*)swR; float4 swN = *(const float4*)(swR - W136);
    float swNr = swR[-W136 + 4];

    float eOa[4]  = {eO.x, eO.y, eO.z, eO.w};
    float sOa[4]  = {sO.x, sO.y, sO.z, sO.w};
    float sNa[4]  = {sN.x, sN.y, sN.z, sN.w};
    float seOa[4] = {seO.x, seO.y, seO.z, seO.w};
    float seNa[4] = {seN.x, seN.y, seN.z, seN.w};
    float swOa[4] = {swO.x, swO.y, swO.z, swO.w};
    float swNa[4] = {swN.x, swN.y, swN.z, swN.w};

    #pragma unroll
    for (int i = 0; i < 4; ++i) {
        float wW  = (i == 0) ? eWl  : eOa[i - 1];
        float wNW = (i == 0) ? seNl : seNa[i - 1];
        float wNE = (i == 3) ? swNr : swNa[i + 1];
        float acc = 3.0f * mw[i + 1];
        acc += eOa[i]  * mw[i + 2];   // E
        acc += wW      * mw[i];       // W
        acc += sOa[i]  * bw[i + 1];   // S
        acc += sNa[i]  * tw[i + 1];   // N
        acc += seOa[i] * bw[i + 2];   // SE
        acc += wNW     * tw[i];       // NW
        acc += swOa[i] * bw[i];       // SW
        acc += wNE     * tw[i + 2];   // NE
        m[i] = acc;
    }
}

__global__ void __cluster_dims__(2, 1, 1) __launch_bounds__(1024, 1)
crf_persistent(const float* __restrict__ x, const float* __restrict__ tg,
               float* __restrict__ out_masks) {
    extern __shared__ float sm[];
    float* wEp  = sm;
    float* wSp  = sm + PLW;
    float* wSEp = sm + 2 * PLW;
    float* wSWp = sm + 3 * PLW;
    float* st0  = sm + 4 * PLW;
    float* st1  = st0 + PLS;

    int t  = threadIdx.x;
    int b  = blockIdx.x >> 1;
    uint32_t r = blockIdx.x & 1;
    int lr = t >> 4;              // 0..63 local row
    int c  = (t & 15) << 3;       // 0..120 col base (8 px/thread)
    int gr = (int)r * 64 + lr;
    size_t gpix = (size_t)b * HW + (size_t)gr * 128 + c;
    int so = (lr + 1) * W136 + 4 + c;   // smem interior offset

    // zero everything (halos must be 0 and stay 0)
    for (int i = t; i < SMF; i += 1024) sm[i] = 0.0f;
    __syncthreads();

    // load weight planes (own row)
    *(float4*)(wEp  + so)     = *(const float4*)(g_wE  + gpix);
    *(float4*)(wEp  + so + 4) = *(const float4*)(g_wE  + gpix + 4);
    *(float4*)(wSp  + so)     = *(const float4*)(g_wS  + gpix);
    *(float4*)(wSp  + so + 4) = *(const float4*)(g_wS  + gpix + 4);
    *(float4*)(wSEp + so)     = *(const float4*)(g_wSE + gpix);
    *(float4*)(wSEp + so + 4) = *(const float4*)(g_wSE + gpix + 4);
    *(float4*)(wSWp + so)     = *(const float4*)(g_wSW + gpix);
    *(float4*)(wSWp + so + 4) = *(const float4*)(g_wSW + gpix + 4);
    if (lr == 0 && gr > 0) {   // top halo weight row (S/SE/SW only)
        size_t hp = gpix - 128;
        int ho = 4 + c;        // plane row 0
        *(float4*)(wSp  + ho)     = *(const float4*)(g_wS  + hp);
        *(float4*)(wSp  + ho + 4) = *(const float4*)(g_wS  + hp + 4);
        *(float4*)(wSEp + ho)     = *(const float4*)(g_wSE + hp);
        *(float4*)(wSEp + ho + 4) = *(const float4*)(g_wSE + hp + 4);
        *(float4*)(wSWp + ho)     = *(const float4*)(g_wSW + hp);
        *(float4*)(wSWp + ho + 4) = *(const float4*)(g_wSW + hp + 4);
    }

    // init state (+-1) and target bits
    bool bnd = (r == 0) ? (lr == 63) : (lr == 0);
    int  prow = (r == 0) ? 0 : 65;
    unsigned tb = 0;
    {
        float4 xa = *(const float4*)(x + gpix);
        float4 xb = *(const float4*)(x + gpix + 4);
        float4 ta = *(const float4*)(tg + gpix);
        float4 tb4 = *(const float4*)(tg + gpix + 4);
        float xs[8] = {xa.x, xa.y, xa.z, xa.w, xb.x, xb.y, xb.z, xb.w};
        float ts[8] = {ta.x, ta.y, ta.z, ta.w, tb4.x, tb4.y, tb4.z, tb4.w};
        float sig[8];
        #pragma unroll
        for (int i = 0; i < 8; ++i) {
            if (ts[i] > 0.5f) tb |= (1u << i);
            sig[i] = (xs[i] * ts[i] > 0.5f) ? 1.0f : -1.0f;
        }
        *(float4*)(st0 + so)     = make_float4(sig[0], sig[1], sig[2], sig[3]);
        *(float4*)(st0 + so + 4) = make_float4(sig[4], sig[5], sig[6], sig[7]);
        if (bnd) {
            uint32_t la = (uint32_t)__cvta_generic_to_shared(st0 + prow * W136 + 4 + c);
            #pragma unroll
            for (int i = 0; i < 8; ++i) st_peer_f32(la + 4u * i, r ^ 1u, sig[i]);
        }
    }
    cluster_sync_();

    const float* A = st0;
    float* B = st1;
    unsigned newmask = 0;
    for (int it = 0; it < 10; ++it) {
        float m[8];
        group4(A, wEp, wSp, wSEp, wSWp, so,     m);
        group4(A, wEp, wSp, wSEp, wSWp, so + 4, m + 4);
        newmask = 0;
        #pragma unroll
        for (int i = 0; i < 8; ++i)
            if (m[i] > 0.0f && ((tb >> i) & 1u)) newmask |= (1u << i);

        if (it < 9) {
            float sig[8];
            #pragma unroll
            for (int i = 0; i < 8; ++i)
                sig[i] = ((newmask >> i) & 1u) ? 1.0f : -1.0f;
            *(float4*)(B + so)     = make_float4(sig[0], sig[1], sig[2], sig[3]);
            *(float4*)(B + so + 4) = make_float4(sig[4], sig[5], sig[6], sig[7]);
            if (bnd) {
                uint32_t la = (uint32_t)__cvta_generic_to_shared(B + prow * W136 + 4 + c);
                #pragma unroll
                for (int i = 0; i < 8; ++i) st_peer_f32(la + 4u * i, r ^ 1u, sig[i]);
            }
            cluster_sync_();
            const float* tmp = A; A = B; B = (float*)tmp;
        }
    }

    // final outputs
    float o[8];
    #pragma unroll
    for (int i = 0; i < 8; ++i) o[i] = ((newmask >> i) & 1u) ? 1.0f : 0.0f;
    *(float4*)(out_masks + gpix)     = make_float4(o[0], o[1], o[2], o[3]);
    *(float4*)(out_masks + gpix + 4) = make_float4(o[4], o[5], o[6], o[7]);

    unsigned p = __popc(newmask);
    #pragma unroll
    for (int off = 16; off; off >>= 1) p += __shfl_down_sync(0xffffffffu, p, off);
    if ((t & 31) == 0) atomicAdd(&g_cnt[b], (int)p);
}

__global__ void valid_small(float* __restrict__ out_valid) {
    int b = threadIdx.x;
    if (b < NB) {
        float c = (float)g_cnt[b];
        out_valid[b] = (c >= 16384.0f * 0.05f && c <= 16384.0f * 0.95f) ? 1.0f : 0.0f;
    }
}

// ================= launch =================

extern "C" void kernel_launch(void* const* d_in, const int* in_sizes, int n_in,
                              void* d_out, int out_size) {
    const float* seg_masks   = (const float*)d_in[0];
    const float* cate_scores = (const float*)d_in[1];
    const float* feature_map = (const float*)d_in[2];
    const float* x           = (const float*)d_in[3];
    const float* targets     = (const float*)d_in[4];
    const int*   cate_labels = (const int*)d_in[5];

    float* out_scores = (float*)d_out;                  // [256]
    float* out_masks  = out_scores + NMS_N;             // [64*128*128]
    float* out_valid  = out_masks + NPIX;               // [64]

    // ---- NMS (also zeroes g_cnt) ----
    pack_kernel<<<NMS_N, 512>>>(seg_masks);
    nms_iou_kernel<<<NMS_N, NMS_N>>>(cate_labels);
    nms_coef_kernel<<<NMS_N, NMS_N>>>(cate_scores, out_scores);

    // ---- CRF weights ----
    crf_weights_kernel<<<NPIX / 256, 256>>>(feature_map);

    // ---- persistent CRF (all 10 iterations) ----
    cudaFuncSetAttribute(crf_persistent, cudaFuncAttributeMaxDynamicSharedMemorySize,
                         SMF * (int)sizeof(float));
    crf_persistent<<<2 * NB, 1024, SMF * sizeof(float)>>>(x, targets, out_masks);

    valid_small<<<1, 64>>>(out_valid);
}

// round 5
// speedup vs baseline: 1.2292x; 1.2292x over previous
#include <cuda_runtime.h>
#include <cuda_bf16.h>
#include <math.h>
#include <stdint.h>

// ---------------- problem sizes ----------------
#define NMS_N   256
#define HW      16384          // 128*128
#define WORDS   512            // 16384/32
#define NB      64             // batch for CRF
#define NPIX    (NB*HW)        // 1,048,576

// ---------------- smem layout for persistent CRF ----------------
#define W136    136                         // padded row stride (4 left pad, 4 right pad)
#define PLW     (65*W136)                   // weight plane: 1 top-halo row + 64 rows
#define PLS     (66*W136)                   // state plane: top halo + 64 + bottom halo
#define SMF     (4*PLW + 2*PLS)             // 53312 floats
#define SMTOT   (SMF + 8)                   // + flag slots

// ---------------- device scratch (static, no allocation) ----------------
__device__ unsigned int g_packed[NMS_N * WORDS];   // [mask][word]
__device__ float        g_sums[NMS_N];
__device__ float        g_dmat[NMS_N * NMS_N];
__device__ float        g_comp[NMS_N];

__device__ __align__(16) float g_wE [NPIX];
__device__ __align__(16) float g_wS [NPIX];
__device__ __align__(16) float g_wSE[NPIX];
__device__ __align__(16) float g_wSW[NPIX];
__device__ int g_cnt[NB];

// ================= helpers =================

__device__ __forceinline__ void cluster_sync_() {
    asm volatile("barrier.cluster.arrive.aligned;" ::: "memory");
    asm volatile("barrier.cluster.wait.aligned;" ::: "memory");
}

__device__ __forceinline__ void st_peer_f32(uint32_t local_addr, uint32_t peer_rank, float v) {
    uint32_t rem;
    asm volatile("mapa.shared::cluster.u32 %0, %1, %2;"
                 : "=r"(rem) : "r"(local_addr), "r"(peer_rank));
    asm volatile("st.shared::cluster.f32 [%0], %1;" :: "r"(rem), "f"(v) : "memory");
}

// ================= NMS =================

__global__ void pack_kernel(const float* __restrict__ seg) {
    int m   = blockIdx.x;
    int tid = threadIdx.x;         // 512 threads
    int warp = tid >> 5, lane = tid & 31;
    if (blockIdx.x == 0 && tid < NB) g_cnt[tid] = 0;
    int cnt = 0;
    for (int w = warp; w < WORDS; w += 16) {
        float v = seg[(size_t)m * HW + w * 32 + lane];
        unsigned bal = __ballot_sync(0xffffffffu, v != 0.0f);
        if (lane == 0) {
            g_packed[m * WORDS + w] = bal;       // [mask][word]
            cnt += __popc(bal);
        }
    }
    __shared__ int scnt[16];
    if (lane == 0) scnt[warp] = cnt;
    __syncthreads();
    if (tid == 0) {
        int t = 0;
        for (int i = 0; i < 16; ++i) t += scnt[i];
        g_sums[m] = (float)t;
    }
}

__global__ void nms_iou_kernel(const int* __restrict__ labels) {
    int j = blockIdx.x;
    int i = threadIdx.x;
    __shared__ uint4 smj[WORDS / 4];     // 128 uint4
    if (i < WORDS / 4)
        smj[i] = ((const uint4*)(g_packed + (size_t)j * WORDS))[i];
    __syncthreads();

    float d = 0.0f;
    if (i < j && labels[i] == labels[j]) {
        const uint4* mi = (const uint4*)(g_packed + (size_t)i * WORDS);
        int inter = 0;
        #pragma unroll 8
        for (int w = 0; w < WORDS / 4; ++w) {
            uint4 a = mi[w];
            uint4 b = smj[w];
            inter += __popc(a.x & b.x) + __popc(a.y & b.y)
                   + __popc(a.z & b.z) + __popc(a.w & b.w);
        }
        float fi  = (float)inter;
        float uni = g_sums[j] + g_sums[i] - fi;
        d = fi / uni;
    }
    g_dmat[j * NMS_N + i] = d;

    __shared__ float red[NMS_N];
    red[i] = d;
    __syncthreads();
    for (int s = NMS_N / 2; s > 0; s >>= 1) {
        if (i < s) red[i] = fmaxf(red[i], red[i + s]);
        __syncthreads();
    }
    if (i == 0) g_comp[j] = red[0];
}

__global__ void nms_coef_kernel(const float* __restrict__ cate_scores,
                                float* __restrict__ out_scores) {
    int j = blockIdx.x;
    int i = threadIdx.x;
    float d  = g_dmat[j * NMS_N + i];
    float ci = g_comp[i];
    float v  = expf(-2.0f * d * d) / expf(-2.0f * ci * ci);
    __shared__ float red[NMS_N];
    red[i] = v;
    __syncthreads();
    for (int s = NMS_N / 2; s > 0; s >>= 1) {
        if (i < s) red[i] = fminf(red[i], red[i + s]);
        __syncthreads();
    }
    if (i == 0) out_scores[j] = cate_scores[j] * red[0];
}

// ================= CRF weights (exact, unchanged math) =================

__global__ void crf_weights_kernel(const float* __restrict__ fm) {
    int idx = blockIdx.x * blockDim.x + threadIdx.x;
    if (idx >= NPIX) return;
    int b   = idx >> 14;
    int pix = idx & (HW - 1);
    int h   = pix >> 7, w = pix & 127;

    const float* fb = fm + (size_t)b * 3 * HW;
    float c0 = fb[pix] + 10.0f;
    float c1 = fb[HW + pix] + 10.0f;
    float c2 = fb[2 * HW + pix] + 10.0f;

    const int   di[4]  = {0, 1, 1, 1};
    const int   dj[4]  = {1, 0, 1, -1};
    const float sp[4]  = {1.0f / 1800.0f, 1.0f / 1800.0f, 2.0f / 1800.0f, 2.0f / 1800.0f};
    float wv[4];
    #pragma unroll
    for (int k = 0; k < 4; ++k) {
        int hh = h + di[k], ww = w + dj[k];
        float v = 0.0f;
        if (hh < 128 && ww >= 0 && ww < 128) {
            int np = hh * 128 + ww;
            float d0 = (fb[np] + 10.0f) - c0;
            float d1 = (fb[HW + np] + 10.0f) - c1;
            float d2 = (fb[2 * HW + np] + 10.0f) - c2;
            float ss = d0 * d0 + d1 * d1 + d2 * d2;
            v = 3.0f * expf(-ss * 2.0f - sp[k]);
        }
        wv[k] = v;
    }
    g_wE [idx] = wv[0];
    g_wS [idx] = wv[1];
    g_wSE[idx] = wv[2];
    g_wSW[idx] = wv[3];
}

// ================= persistent CRF =================

__device__ __forceinline__ void group4(const float* __restrict__ A,
                                       const float* __restrict__ wEp,
                                       const float* __restrict__ wSp,
                                       const float* __restrict__ wSEp,
                                       const float* __restrict__ wSWp,
                                       int ro, float m[4]) {
    const float* Ar = A + ro;
    float4 cu = *(const float4*)(Ar - W136);
    float4 cm = *(const float4*)(Ar);
    float4 cd = *(const float4*)(Ar + W136);
    float lu = Ar[-W136 - 1], ru = Ar[-W136 + 4];
    float lm = Ar[-1],        rm = Ar[4];
    float ldv = Ar[W136 - 1], rd = Ar[W136 + 4];

    float tw[6] = {lu,  cu.x, cu.y, cu.z, cu.w, ru};
    float mw[6] = {lm,  cm.x, cm.y, cm.z, cm.w, rm};
    float bw[6] = {ldv, cd.x, cd.y, cd.z, cd.w, rd};

    const float* eR = wEp + ro;
    float4 eO = *(const float4*)eR;  float eWl = eR[-1];
    const float* sR = wSp + ro;
    float4 sO = *(const float4*)sR;  float4 sN = *(const float4*)(sR - W136);
    const float* seR = wSEp + ro;
    float4 seO = *(const float4*)seR; float4 seN = *(const float4*)(seR - W136);
    float seNl = seR[-W136 - 1];
    const float* swR = wSWp + ro;
    float4 swO = *(const float4*)swR; float4 swN = *(const float4*)(swR - W136);
    float swNr = swR[-W136 + 4];

    float eOa[4]  = {eO.x, eO.y, eO.z, eO.w};
    float sOa[4]  = {sO.x, sO.y, sO.z, sO.w};
    float sNa[4]  = {sN.x, sN.y, sN.z, sN.w};
    float seOa[4] = {seO.x, seO.y, seO.z, seO.w};
    float seNa[4] = {seN.x, seN.y, seN.z, seN.w};
    float swOa[4] = {swO.x, swO.y, swO.z, swO.w};
    float swNa[4] = {swN.x, swN.y, swN.z, swN.w};

    #pragma unroll
    for (int i = 0; i < 4; ++i) {
        float wW  = (i == 0) ? eWl  : eOa[i - 1];
        float wNW = (i == 0) ? seNl : seNa[i - 1];
        float wNE = (i == 3) ? swNr : swNa[i + 1];
        float acc = 3.0f * mw[i + 1];
        acc += eOa[i]  * mw[i + 2];   // E
        acc += wW      * mw[i];       // W
        acc += sOa[i]  * bw[i + 1];   // S
        acc += sNa[i]  * tw[i + 1];   // N
        acc += seOa[i] * bw[i + 2];   // SE
        acc += wNW     * tw[i];       // NW
        acc += swOa[i] * bw[i];       // SW
        acc += wNE     * tw[i + 2];   // NE
        m[i] = acc;
    }
}

__global__ void __cluster_dims__(2, 1, 1) __launch_bounds__(1024, 1)
crf_persistent(const float* __restrict__ x, const float* __restrict__ tg,
               float* __restrict__ out_masks) {
    extern __shared__ float sm[];
    float* wEp  = sm;
    float* wSp  = sm + PLW;
    float* wSEp = sm + 2 * PLW;
    float* wSWp = sm + 3 * PLW;
    float* st0  = sm + 4 * PLW;
    float* st1  = st0 + PLS;
    float* flag = sm + SMF;            // flag[0]: peer-written change flag

    int t  = threadIdx.x;
    int b  = blockIdx.x >> 1;
    uint32_t r = blockIdx.x & 1;
    int lr = t >> 4;              // 0..63 local row
    int c  = (t & 15) << 3;       // 0..120 col base (8 px/thread)
    int gr = (int)r * 64 + lr;
    size_t gpix = (size_t)b * HW + (size_t)gr * 128 + c;
    int so = (lr + 1) * W136 + 4 + c;   // smem interior offset

    // zero everything (halos must be 0 and stay 0)
    for (int i = t; i < SMTOT; i += 1024) sm[i] = 0.0f;
    __syncthreads();

    // load weight planes (own row)
    *(float4*)(wEp  + so)     = *(const float4*)(g_wE  + gpix);
    *(float4*)(wEp  + so + 4) = *(const float4*)(g_wE  + gpix + 4);
    *(float4*)(wSp  + so)     = *(const float4*)(g_wS  + gpix);
    *(float4*)(wSp  + so + 4) = *(const float4*)(g_wS  + gpix + 4);
    *(float4*)(wSEp + so)     = *(const float4*)(g_wSE + gpix);
    *(float4*)(wSEp + so + 4) = *(const float4*)(g_wSE + gpix + 4);
    *(float4*)(wSWp + so)     = *(const float4*)(g_wSW + gpix);
    *(float4*)(wSWp + so + 4) = *(const float4*)(g_wSW + gpix + 4);
    if (lr == 0 && gr > 0) {   // top halo weight row (S/SE/SW mirrors)
        size_t hp = gpix - 128;
        int ho = 4 + c;        // plane row 0
        *(float4*)(wSp  + ho)     = *(const float4*)(g_wS  + hp);
        *(float4*)(wSp  + ho + 4) = *(const float4*)(g_wS  + hp + 4);
        *(float4*)(wSEp + ho)     = *(const float4*)(g_wSE + hp);
        *(float4*)(wSEp + ho + 4) = *(const float4*)(g_wSE + hp + 4);
        *(float4*)(wSWp + ho)     = *(const float4*)(g_wSW + hp);
        *(float4*)(wSWp + ho + 4) = *(const float4*)(g_wSW + hp + 4);
    }

    // init state (+-1) and target bits
    bool bnd = (r == 0) ? (lr == 63) : (lr == 0);
    int  prow = (r == 0) ? 0 : 65;
    unsigned tb = 0, prevmask = 0;
    {
        float4 xa = *(const float4*)(x + gpix);
        float4 xb = *(const float4*)(x + gpix + 4);
        float4 ta = *(const float4*)(tg + gpix);
        float4 tb4 = *(const float4*)(tg + gpix + 4);
        float xs[8] = {xa.x, xa.y, xa.z, xa.w, xb.x, xb.y, xb.z, xb.w};
        float ts[8] = {ta.x, ta.y, ta.z, ta.w, tb4.x, tb4.y, tb4.z, tb4.w};
        float sig[8];
        #pragma unroll
        for (int i = 0; i < 8; ++i) {
            if (ts[i] > 0.5f) tb |= (1u << i);
            bool on = (xs[i] * ts[i] > 0.5f);
            if (on) prevmask |= (1u << i);
            sig[i] = on ? 1.0f : -1.0f;
        }
        *(float4*)(st0 + so)     = make_float4(sig[0], sig[1], sig[2], sig[3]);
        *(float4*)(st0 + so + 4) = make_float4(sig[4], sig[5], sig[6], sig[7]);
        if (bnd) {
            uint32_t la = (uint32_t)__cvta_generic_to_shared(st0 + prow * W136 + 4 + c);
            #pragma unroll
            for (int i = 0; i < 8; ++i) st_peer_f32(la + 4u * i, r ^ 1u, sig[i]);
        }
    }
    uint32_t flag_addr = (uint32_t)__cvta_generic_to_shared(flag);
    cluster_sync_();

    const float* A = st0;
    float* B = st1;
    unsigned newmask = prevmask;
    for (int it = 0; it < 10; ++it) {
        float m[8];
        group4(A, wEp, wSp, wSEp, wSWp, so,     m);
        group4(A, wEp, wSp, wSEp, wSWp, so + 4, m + 4);
        newmask = 0;
        #pragma unroll
        for (int i = 0; i < 8; ++i)
            if (m[i] > 0.0f && ((tb >> i) & 1u)) newmask |= (1u << i);

        int changed = (newmask != prevmask) ? 1 : 0;
        prevmask = newmask;
        int blkchg = __syncthreads_or(changed);
        if (it == 9) break;

        // write new states + halo exchange
        float sig[8];
        #pragma unroll
        for (int i = 0; i < 8; ++i)
            sig[i] = ((newmask >> i) & 1u) ? 1.0f : -1.0f;
        *(float4*)(B + so)     = make_float4(sig[0], sig[1], sig[2], sig[3]);
        *(float4*)(B + so + 4) = make_float4(sig[4], sig[5], sig[6], sig[7]);
        if (bnd) {
            uint32_t la = (uint32_t)__cvta_generic_to_shared(B + prow * W136 + 4 + c);
            #pragma unroll
            for (int i = 0; i < 8; ++i) st_peer_f32(la + 4u * i, r ^ 1u, sig[i]);
        }
        if (t == 0)
            st_peer_f32(flag_addr, r ^ 1u, blkchg ? 1.0f : 0.0f);
        cluster_sync_();
        bool peerchg = (flag[0] != 0.0f);
        if (!blkchg && !peerchg) break;   // exact fixed point across cluster
        const float* tmp = A; A = B; B = (float*)tmp;
    }

    // final outputs
    float o[8];
    #pragma unroll
    for (int i = 0; i < 8; ++i) o[i] = ((newmask >> i) & 1u) ? 1.0f : 0.0f;
    *(float4*)(out_masks + gpix)     = make_float4(o[0], o[1], o[2], o[3]);
    *(float4*)(out_masks + gpix + 4) = make_float4(o[4], o[5], o[6], o[7]);

    unsigned p = __popc(newmask);
    #pragma unroll
    for (int off = 16; off; off >>= 1) p += __shfl_down_sync(0xffffffffu, p, off);
    if ((t & 31) == 0) atomicAdd(&g_cnt[b], (int)p);
}

__global__ void valid_small(float* __restrict__ out_valid) {
    int b = threadIdx.x;
    if (b < NB) {
        float c = (float)g_cnt[b];
        out_valid[b] = (c >= 16384.0f * 0.05f && c <= 16384.0f * 0.95f) ? 1.0f : 0.0f;
    }
}

// ================= launch =================

extern "C" void kernel_launch(void* const* d_in, const int* in_sizes, int n_in,
                              void* d_out, int out_size) {
    const float* seg_masks   = (const float*)d_in[0];
    const float* cate_scores = (const float*)d_in[1];
    const float* feature_map = (const float*)d_in[2];
    const float* x           = (const float*)d_in[3];
    const float* targets     = (const float*)d_in[4];
    const int*   cate_labels = (const int*)d_in[5];

    float* out_scores = (float*)d_out;                  // [256]
    float* out_masks  = out_scores + NMS_N;             // [64*128*128]
    float* out_valid  = out_masks + NPIX;               // [64]

    // ---- NMS (also zeroes g_cnt) ----
    pack_kernel<<<NMS_N, 512>>>(seg_masks);
    nms_iou_kernel<<<NMS_N, NMS_N>>>(cate_labels);
    nms_coef_kernel<<<NMS_N, NMS_N>>>(cate_scores, out_scores);

    // ---- CRF weights ----
    crf_weights_kernel<<<NPIX / 256, 256>>>(feature_map);

    // ---- persistent CRF (up to 10 iterations, exact early-exit) ----
    cudaFuncSetAttribute(crf_persistent, cudaFuncAttributeMaxDynamicSharedMemorySize,
                         SMTOT * (int)sizeof(float));
    crf_persistent<<<2 * NB, 1024, SMTOT * sizeof(float)>>>(x, targets, out_masks);

    valid_small<<<1, 64>>>(out_valid);
}

// round 6
// speedup vs baseline: 1.5000x; 1.2203x over previous
#include <cuda_runtime.h>
#include <cuda_bf16.h>
#include <math.h>
#include <stdint.h>

// ---------------- problem sizes ----------------
#define NMS_N   256
#define HW      16384          // 128*128
#define WORDS   512            // 16384/32
#define NB      64             // batch for CRF
#define NPIX    (NB*HW)        // 1,048,576

// ---------------- smem layout for persistent CRF ----------------
#define W136    136                         // padded row stride (4 left, 4 right pad)
#define PLW     (65*W136)                   // weight plane: halo row + 64 rows
#define PLS     (66*W136)                   // state plane: halo + 64 + halo
#define SMF     (4*PLW + 2*PLS)             // 53312 floats
#define SMTOT   (SMF + 8)                   // + 2 ping-pong flag slots

// ---------------- device scratch (static, no allocation) ----------------
__device__ unsigned int g_packed[NMS_N * WORDS];   // [mask][word]
__device__ float        g_sums[NMS_N];
__device__ float        g_dmat[NMS_N * NMS_N];
__device__ float        g_comp[NMS_N];
__device__ int          g_cnt[NB];

// ================= helpers =================

__device__ __forceinline__ void cluster_sync_() {
    asm volatile("barrier.cluster.arrive.aligned;" ::: "memory");
    asm volatile("barrier.cluster.wait.aligned;" ::: "memory");
}

__device__ __forceinline__ void st_peer_f32(uint32_t local_addr, uint32_t peer_rank, float v) {
    uint32_t rem;
    asm volatile("mapa.shared::cluster.u32 %0, %1, %2;"
                 : "=r"(rem) : "r"(local_addr), "r"(peer_rank));
    asm volatile("st.shared::cluster.f32 [%0], %1;" :: "r"(rem), "f"(v) : "memory");
}

// ================= NMS =================

__global__ void pack_kernel(const float* __restrict__ seg) {
    int m   = blockIdx.x;
    int tid = threadIdx.x;         // 512 threads
    int warp = tid >> 5, lane = tid & 31;
    if (blockIdx.x == 0 && tid < NB) g_cnt[tid] = 0;
    int cnt = 0;
    for (int w = warp; w < WORDS; w += 16) {
        float v = seg[(size_t)m * HW + w * 32 + lane];
        unsigned bal = __ballot_sync(0xffffffffu, v != 0.0f);
        if (lane == 0) {
            g_packed[m * WORDS + w] = bal;
            cnt += __popc(bal);
        }
    }
    __shared__ int scnt[16];
    if (lane == 0) scnt[warp] = cnt;
    __syncthreads();
    if (tid == 0) {
        int t = 0;
        for (int i = 0; i < 16; ++i) t += scnt[i];
        g_sums[m] = (float)t;
    }
}

__global__ void nms_iou_kernel(const int* __restrict__ labels) {
    int j = blockIdx.x;
    int i = threadIdx.x;
    __shared__ uint4 smj[WORDS / 4];
    if (i < WORDS / 4)
        smj[i] = ((const uint4*)(g_packed + (size_t)j * WORDS))[i];
    __syncthreads();

    float d = 0.0f;
    if (i < j && labels[i] == labels[j]) {
        const uint4* mi = (const uint4*)(g_packed + (size_t)i * WORDS);
        int inter = 0;
        #pragma unroll 8
        for (int w = 0; w < WORDS / 4; ++w) {
            uint4 a = mi[w];
            uint4 b = smj[w];
            inter += __popc(a.x & b.x) + __popc(a.y & b.y)
                   + __popc(a.z & b.z) + __popc(a.w & b.w);
        }
        float fi  = (float)inter;
        float uni = g_sums[j] + g_sums[i] - fi;
        d = fi / uni;
    }
    g_dmat[j * NMS_N + i] = d;

    __shared__ float red[NMS_N];
    red[i] = d;
    __syncthreads();
    for (int s = NMS_N / 2; s > 0; s >>= 1) {
        if (i < s) red[i] = fmaxf(red[i], red[i + s]);
        __syncthreads();
    }
    if (i == 0) g_comp[j] = red[0];
}

__global__ void nms_coef_kernel(const float* __restrict__ cate_scores,
                                float* __restrict__ out_scores) {
    int j = blockIdx.x;
    int i = threadIdx.x;
    float d  = g_dmat[j * NMS_N + i];
    float ci = g_comp[i];
    float v  = expf(-2.0f * d * d) / expf(-2.0f * ci * ci);
    __shared__ float red[NMS_N];
    red[i] = v;
    __syncthreads();
    for (int s = NMS_N / 2; s > 0; s >>= 1) {
        if (i < s) red[i] = fminf(red[i], red[i + s]);
        __syncthreads();
    }
    if (i == 0) out_scores[j] = cate_scores[j] * red[0];
}

// ================= CRF =================

// Compute the 4 stored direction weights for 8 pixels of global row gr_
// (cols c..c+7). Float ops identical to the original weights kernel.
__device__ __forceinline__ void weights_row8(const float* __restrict__ fb,
                                             int gr_, int c,
                                             float wE[8], float wS[8],
                                             float wSE[8], float wSW[8]) {
    float o0[10], o1[10], o2[10];   // own row, cols c-? : idx1..9 = c..c+8
    float m0[10], m1[10], m2[10];   // next row, idx0..9 = c-1..c+8
    size_t p = (size_t)gr_ * 128 + c;
    {
        float4 a = *(const float4*)(fb + p);
        float4 b4 = *(const float4*)(fb + p + 4);
        o0[1]=a.x+10.0f; o0[2]=a.y+10.0f; o0[3]=a.z+10.0f; o0[4]=a.w+10.0f;
        o0[5]=b4.x+10.0f; o0[6]=b4.y+10.0f; o0[7]=b4.z+10.0f; o0[8]=b4.w+10.0f;
        o0[9]=(c<120)? fb[p+8]+10.0f : 0.0f;
        a = *(const float4*)(fb + HW + p); b4 = *(const float4*)(fb + HW + p + 4);
        o1[1]=a.x+10.0f; o1[2]=a.y+10.0f; o1[3]=a.z+10.0f; o1[4]=a.w+10.0f;
        o1[5]=b4.x+10.0f; o1[6]=b4.y+10.0f; o1[7]=b4.z+10.0f; o1[8]=b4.w+10.0f;
        o1[9]=(c<120)? fb[HW+p+8]+10.0f : 0.0f;
        a = *(const float4*)(fb + 2*HW + p); b4 = *(const float4*)(fb + 2*HW + p + 4);
        o2[1]=a.x+10.0f; o2[2]=a.y+10.0f; o2[3]=a.z+10.0f; o2[4]=a.w+10.0f;
        o2[5]=b4.x+10.0f; o2[6]=b4.y+10.0f; o2[7]=b4.z+10.0f; o2[8]=b4.w+10.0f;
        o2[9]=(c<120)? fb[2*HW+p+8]+10.0f : 0.0f;
    }
    bool hn = (gr_ < 127);
    if (hn) {
        size_t q = p + 128;
        float4 a = *(const float4*)(fb + q);
        float4 b4 = *(const float4*)(fb + q + 4);
        m0[0]=(c>0)? fb[q-1]+10.0f : 0.0f;
        m0[1]=a.x+10.0f; m0[2]=a.y+10.0f; m0[3]=a.z+10.0f; m0[4]=a.w+10.0f;
        m0[5]=b4.x+10.0f; m0[6]=b4.y+10.0f; m0[7]=b4.z+10.0f; m0[8]=b4.w+10.0f;
        m0[9]=(c<120)? fb[q+8]+10.0f : 0.0f;
        a = *(const float4*)(fb + HW + q); b4 = *(const float4*)(fb + HW + q + 4);
        m1[0]=(c>0)? fb[HW+q-1]+10.0f : 0.0f;
        m1[1]=a.x+10.0f; m1[2]=a.y+10.0f; m1[3]=a.z+10.0f; m1[4]=a.w+10.0f;
        m1[5]=b4.x+10.0f; m1[6]=b4.y+10.0f; m1[7]=b4.z+10.0f; m1[8]=b4.w+10.0f;
        m1[9]=(c<120)? fb[HW+q+8]+10.0f : 0.0f;
        a = *(const float4*)(fb + 2*HW + q); b4 = *(const float4*)(fb + 2*HW + q + 4);
        m2[0]=(c>0)? fb[2*HW+q-1]+10.0f : 0.0f;
        m2[1]=a.x+10.0f; m2[2]=a.y+10.0f; m2[3]=a.z+10.0f; m2[4]=a.w+10.0f;
        m2[5]=b4.x+10.0f; m2[6]=b4.y+10.0f; m2[7]=b4.z+10.0f; m2[8]=b4.w+10.0f;
        m2[9]=(c<120)? fb[2*HW+q+8]+10.0f : 0.0f;
    } else {
        #pragma unroll
        for (int i = 0; i < 10; ++i) { m0[i]=0.0f; m1[i]=0.0f; m2[i]=0.0f; }
    }

    const float spE  = 1.0f / 1800.0f;
    const float spS  = 1.0f / 1800.0f;
    const float spSE = 2.0f / 1800.0f;
    const float spSW = 2.0f / 1800.0f;
    #pragma unroll
    for (int j = 0; j < 8; ++j) {
        float c0 = o0[j+1], c1 = o1[j+1], c2 = o2[j+1];
        // E: neighbor (gr_, c+j+1)
        {
            bool inb = (c + j + 1) < 128;
            float d0 = o0[j+2]-c0, d1 = o1[j+2]-c1, d2 = o2[j+2]-c2;
            float ss = d0*d0 + d1*d1 + d2*d2;
            wE[j] = inb ? 3.0f * expf(-ss*2.0f - spE) : 0.0f;
        }
        // S
        {
            float d0 = m0[j+1]-c0, d1 = m1[j+1]-c1, d2 = m2[j+1]-c2;
            float ss = d0*d0 + d1*d1 + d2*d2;
            wS[j] = hn ? 3.0f * expf(-ss*2.0f - spS) : 0.0f;
        }
        // SE
        {
            bool inb = hn && ((c + j + 1) < 128);
            float d0 = m0[j+2]-c0, d1 = m1[j+2]-c1, d2 = m2[j+2]-c2;
            float ss = d0*d0 + d1*d1 + d2*d2;
            wSE[j] = inb ? 3.0f * expf(-ss*2.0f - spSE) : 0.0f;
        }
        // SW
        {
            bool inb = hn && ((c + j - 1) >= 0);
            float d0 = m0[j]-c0, d1 = m1[j]-c1, d2 = m2[j]-c2;
            float ss = d0*d0 + d1*d1 + d2*d2;
            wSW[j] = inb ? 3.0f * expf(-ss*2.0f - spSW) : 0.0f;
        }
    }
}

// One Jacobi update for 8 pixels at smem interior offset ro. Returns 8 mask bits.
__device__ __forceinline__ unsigned iter_row8(const float* __restrict__ A,
                                              const float* __restrict__ wEp,
                                              const float* __restrict__ wSp,
                                              const float* __restrict__ wSEp,
                                              const float* __restrict__ wSWp,
                                              int ro, unsigned tb8) {
    const float* Ar = A + ro;
    float tw[10], mw[10], bw[10];
    {
        float4 a = *(const float4*)(Ar - W136), b4 = *(const float4*)(Ar - W136 + 4);
        tw[0]=Ar[-W136-1];
        tw[1]=a.x; tw[2]=a.y; tw[3]=a.z; tw[4]=a.w;
        tw[5]=b4.x; tw[6]=b4.y; tw[7]=b4.z; tw[8]=b4.w;
        tw[9]=Ar[-W136+8];
        a = *(const float4*)(Ar); b4 = *(const float4*)(Ar + 4);
        mw[0]=Ar[-1];
        mw[1]=a.x; mw[2]=a.y; mw[3]=a.z; mw[4]=a.w;
        mw[5]=b4.x; mw[6]=b4.y; mw[7]=b4.z; mw[8]=b4.w;
        mw[9]=Ar[8];
        a = *(const float4*)(Ar + W136); b4 = *(const float4*)(Ar + W136 + 4);
        bw[0]=Ar[W136-1];
        bw[1]=a.x; bw[2]=a.y; bw[3]=a.z; bw[4]=a.w;
        bw[5]=b4.x; bw[6]=b4.y; bw[7]=b4.z; bw[8]=b4.w;
        bw[9]=Ar[W136+8];
    }
    const float* eR  = wEp  + ro;
    const float* sR  = wSp  + ro;
    const float* seR = wSEp + ro;
    const float* swR = wSWp + ro;
    float4 e0 = *(const float4*)eR, e1 = *(const float4*)(eR + 4);
    float eWl = eR[-1];
    float4 s0 = *(const float4*)sR, s1 = *(const float4*)(sR + 4);
    float4 sn0 = *(const float4*)(sR - W136), sn1 = *(const float4*)(sR - W136 + 4);
    float4 se0 = *(const float4*)seR, se1 = *(const float4*)(seR + 4);
    float4 sen0 = *(const float4*)(seR - W136), sen1 = *(const float4*)(seR - W136 + 4);
    float seNl = seR[-W136 - 1];
    float4 sw0 = *(const float4*)swR, sw1 = *(const float4*)(swR + 4);
    float4 swn0 = *(const float4*)(swR - W136), swn1 = *(const float4*)(swR - W136 + 4);
    float swNr = swR[-W136 + 8];

    float eA[8]  = {e0.x,e0.y,e0.z,e0.w, e1.x,e1.y,e1.z,e1.w};
    float sO[8]  = {s0.x,s0.y,s0.z,s0.w, s1.x,s1.y,s1.z,s1.w};
    float sN[8]  = {sn0.x,sn0.y,sn0.z,sn0.w, sn1.x,sn1.y,sn1.z,sn1.w};
    float seO[8] = {se0.x,se0.y,se0.z,se0.w, se1.x,se1.y,se1.z,se1.w};
    float seN[8] = {sen0.x,sen0.y,sen0.z,sen0.w, sen1.x,sen1.y,sen1.z,sen1.w};
    float swO[8] = {sw0.x,sw0.y,sw0.z,sw0.w, sw1.x,sw1.y,sw1.z,sw1.w};
    float swN[8] = {swn0.x,swn0.y,swn0.z,swn0.w, swn1.x,swn1.y,swn1.z,swn1.w};

    unsigned nm = 0;
    #pragma unroll
    for (int j = 0; j < 8; ++j) {
        float wW  = j ? eA[j-1]  : eWl;
        float wNW = j ? seN[j-1] : seNl;
        float wNE = (j < 7) ? swN[j+1] : swNr;
        float acc = 3.0f * mw[j+1];
        acc += eA[j]  * mw[j+2];   // E
        acc += wW     * mw[j];     // W
        acc += sO[j]  * bw[j+1];   // S
        acc += sN[j]  * tw[j+1];   // N
        acc += seO[j] * bw[j+2];   // SE
        acc += wNW    * tw[j];     // NW
        acc += swO[j] * bw[j];     // SW
        acc += wNE    * tw[j+2];   // NE
        if (acc > 0.0f && ((tb8 >> j) & 1u)) nm |= (1u << j);
    }
    return nm;
}

__global__ void __cluster_dims__(2, 1, 1) __launch_bounds__(512, 1)
crf_persistent(const float* __restrict__ fm,
               const float* __restrict__ x, const float* __restrict__ tg,
               float* __restrict__ out_masks) {
    extern __shared__ float sm[];
    float* wEp  = sm;
    float* wSp  = sm + PLW;
    float* wSEp = sm + 2 * PLW;
    float* wSWp = sm + 3 * PLW;
    float* st0  = sm + 4 * PLW;
    float* st1  = st0 + PLS;
    float* flag = sm + SMF;            // flag[0],flag[1]: ping-pong peer flags

    int t  = threadIdx.x;              // 512 threads
    int b  = blockIdx.x >> 1;
    uint32_t r = blockIdx.x & 1;
    int tr = t >> 4;                   // 0..31 (2 rows each)
    int c  = (t & 15) << 3;            // col base, 8 px
    int lr0 = tr * 2, lr1 = lr0 + 1;
    int gr0 = (int)r * 64 + lr0, gr1 = gr0 + 1;
    size_t gp0 = (size_t)b * HW + (size_t)gr0 * 128 + c;
    size_t gp1 = gp0 + 128;
    int so0 = (lr0 + 1) * W136 + 4 + c;
    int so1 = so0 + W136;

    for (int i = t; i < SMTOT; i += 512) sm[i] = 0.0f;
    __syncthreads();

    const float* fb = fm + (size_t)b * 3 * HW;

    // ---- compute weights into smem planes ----
    {
        float wE[8], wS[8], wSE[8], wSW[8];
        weights_row8(fb, gr0, c, wE, wS, wSE, wSW);
        *(float4*)(wEp  + so0)   = make_float4(wE[0],wE[1],wE[2],wE[3]);
        *(float4*)(wEp  + so0+4) = make_float4(wE[4],wE[5],wE[6],wE[7]);
        *(float4*)(wSp  + so0)   = make_float4(wS[0],wS[1],wS[2],wS[3]);
        *(float4*)(wSp  + so0+4) = make_float4(wS[4],wS[5],wS[6],wS[7]);
        *(float4*)(wSEp + so0)   = make_float4(wSE[0],wSE[1],wSE[2],wSE[3]);
        *(float4*)(wSEp + so0+4) = make_float4(wSE[4],wSE[5],wSE[6],wSE[7]);
        *(float4*)(wSWp + so0)   = make_float4(wSW[0],wSW[1],wSW[2],wSW[3]);
        *(float4*)(wSWp + so0+4) = make_float4(wSW[4],wSW[5],wSW[6],wSW[7]);

        weights_row8(fb, gr1, c, wE, wS, wSE, wSW);
        *(float4*)(wEp  + so1)   = make_float4(wE[0],wE[1],wE[2],wE[3]);
        *(float4*)(wEp  + so1+4) = make_float4(wE[4],wE[5],wE[6],wE[7]);
        *(float4*)(wSp  + so1)   = make_float4(wS[0],wS[1],wS[2],wS[3]);
        *(float4*)(wSp  + so1+4) = make_float4(wS[4],wS[5],wS[6],wS[7]);
        *(float4*)(wSEp + so1)   = make_float4(wSE[0],wSE[1],wSE[2],wSE[3]);
        *(float4*)(wSEp + so1+4) = make_float4(wSE[4],wSE[5],wSE[6],wSE[7]);
        *(float4*)(wSWp + so1)   = make_float4(wSW[0],wSW[1],wSW[2],wSW[3]);
        *(float4*)(wSWp + so1+4) = make_float4(wSW[4],wSW[5],wSW[6],wSW[7]);

        if (r == 1 && tr == 0) {       // halo row: global row 63 S/SE/SW
            weights_row8(fb, 63, c, wE, wS, wSE, wSW);
            int ho = 4 + c;            // plane row 0
            *(float4*)(wSp  + ho)   = make_float4(wS[0],wS[1],wS[2],wS[3]);
            *(float4*)(wSp  + ho+4) = make_float4(wS[4],wS[5],wS[6],wS[7]);
            *(float4*)(wSEp + ho)   = make_float4(wSE[0],wSE[1],wSE[2],wSE[3]);
            *(float4*)(wSEp + ho+4) = make_float4(wSE[4],wSE[5],wSE[6],wSE[7]);
            *(float4*)(wSWp + ho)   = make_float4(wSW[0],wSW[1],wSW[2],wSW[3]);
            *(float4*)(wSWp + ho+4) = make_float4(wSW[4],wSW[5],wSW[6],wSW[7]);
        }
    }

    // ---- init states (+-1) and target bits ----
    bool bnd0 = (r == 1) && (tr == 0);    // row gr0==64 -> peer bottom halo (row 65)
    bool bnd1 = (r == 0) && (tr == 31);   // row gr1==63 -> peer top halo (row 0)
    unsigned tb = 0, prevmask = 0;
    {
        float4 xa = *(const float4*)(x + gp0);
        float4 xb = *(const float4*)(x + gp0 + 4);
        float4 ta = *(const float4*)(tg + gp0);
        float4 tc = *(const float4*)(tg + gp0 + 4);
        float xs[8] = {xa.x,xa.y,xa.z,xa.w, xb.x,xb.y,xb.z,xb.w};
        float ts[8] = {ta.x,ta.y,ta.z,ta.w, tc.x,tc.y,tc.z,tc.w};
        float sig[8];
        #pragma unroll
        for (int i = 0; i < 8; ++i) {
            if (ts[i] > 0.5f) tb |= (1u << i);
            bool on = (xs[i] * ts[i] > 0.5f);
            if (on) prevmask |= (1u << i);
            sig[i] = on ? 1.0f : -1.0f;
        }
        *(float4*)(st0 + so0)     = make_float4(sig[0],sig[1],sig[2],sig[3]);
        *(float4*)(st0 + so0 + 4) = make_float4(sig[4],sig[5],sig[6],sig[7]);
        if (bnd0) {
            uint32_t la = (uint32_t)__cvta_generic_to_shared(st0 + 65 * W136 + 4 + c);
            #pragma unroll
            for (int i = 0; i < 8; ++i) st_peer_f32(la + 4u*i, r ^ 1u, sig[i]);
        }
        xa = *(const float4*)(x + gp1);  xb = *(const float4*)(x + gp1 + 4);
        ta = *(const float4*)(tg + gp1); tc = *(const float4*)(tg + gp1 + 4);
        float xs2[8] = {xa.x,xa.y,xa.z,xa.w, xb.x,xb.y,xb.z,xb.w};
        float ts2[8] = {ta.x,ta.y,ta.z,ta.w, tc.x,tc.y,tc.z,tc.w};
        #pragma unroll
        for (int i = 0; i < 8; ++i) {
            if (ts2[i] > 0.5f) tb |= (1u << (8 + i));
            bool on = (xs2[i] * ts2[i] > 0.5f);
            if (on) prevmask |= (1u << (8 + i));
            sig[i] = on ? 1.0f : -1.0f;
        }
        *(float4*)(st0 + so1)     = make_float4(sig[0],sig[1],sig[2],sig[3]);
        *(float4*)(st0 + so1 + 4) = make_float4(sig[4],sig[5],sig[6],sig[7]);
        if (bnd1) {
            uint32_t la = (uint32_t)__cvta_generic_to_shared(st0 + 0 * W136 + 4 + c);
            #pragma unroll
            for (int i = 0; i < 8; ++i) st_peer_f32(la + 4u*i, r ^ 1u, sig[i]);
        }
    }
    uint32_t flag_base = (uint32_t)__cvta_generic_to_shared(flag);
    cluster_sync_();

    const float* A = st0;
    float* B = st1;
    unsigned newmask = prevmask;
    for (int it = 0; it < 10; ++it) {
        unsigned nm0 = iter_row8(A, wEp, wSp, wSEp, wSWp, so0, tb & 0xFFu);
        unsigned nm1 = iter_row8(A, wEp, wSp, wSEp, wSWp, so1, (tb >> 8) & 0xFFu);
        newmask = nm0 | (nm1 << 8);

        int changed = (newmask != prevmask) ? 1 : 0;
        prevmask = newmask;
        int blkchg = __syncthreads_or(changed);
        if (it == 9) break;

        float sig[8];
        #pragma unroll
        for (int i = 0; i < 8; ++i) sig[i] = ((nm0 >> i) & 1u) ? 1.0f : -1.0f;
        *(float4*)(B + so0)     = make_float4(sig[0],sig[1],sig[2],sig[3]);
        *(float4*)(B + so0 + 4) = make_float4(sig[4],sig[5],sig[6],sig[7]);
        if (bnd0) {
            uint32_t la = (uint32_t)__cvta_generic_to_shared(B + 65 * W136 + 4 + c);
            #pragma unroll
            for (int i = 0; i < 8; ++i) st_peer_f32(la + 4u*i, r ^ 1u, sig[i]);
        }
        #pragma unroll
        for (int i = 0; i < 8; ++i) sig[i] = ((nm1 >> i) & 1u) ? 1.0f : -1.0f;
        *(float4*)(B + so1)     = make_float4(sig[0],sig[1],sig[2],sig[3]);
        *(float4*)(B + so1 + 4) = make_float4(sig[4],sig[5],sig[6],sig[7]);
        if (bnd1) {
            uint32_t la = (uint32_t)__cvta_generic_to_shared(B + 0 * W136 + 4 + c);
            #pragma unroll
            for (int i = 0; i < 8; ++i) st_peer_f32(la + 4u*i, r ^ 1u, sig[i]);
        }
        if (t == 0)
            st_peer_f32(flag_base + 4u * (it & 1), r ^ 1u, blkchg ? 1.0f : 0.0f);
        cluster_sync_();
        bool peerchg = (flag[it & 1] != 0.0f);
        if (!blkchg && !peerchg) break;   // exact fixed point cluster-wide
        const float* tmp = A; A = B; B = (float*)tmp;
    }

    // ---- final outputs ----
    float o[8];
    #pragma unroll
    for (int i = 0; i < 8; ++i) o[i] = ((newmask >> i) & 1u) ? 1.0f : 0.0f;
    *(float4*)(out_masks + gp0)     = make_float4(o[0],o[1],o[2],o[3]);
    *(float4*)(out_masks + gp0 + 4) = make_float4(o[4],o[5],o[6],o[7]);
    #pragma unroll
    for (int i = 0; i < 8; ++i) o[i] = ((newmask >> (8 + i)) & 1u) ? 1.0f : 0.0f;
    *(float4*)(out_masks + gp1)     = make_float4(o[0],o[1],o[2],o[3]);
    *(float4*)(out_masks + gp1 + 4) = make_float4(o[4],o[5],o[6],o[7]);

    unsigned p = __popc(newmask & 0xFFFFu);
    #pragma unroll
    for (int off = 16; off; off >>= 1) p += __shfl_down_sync(0xffffffffu, p, off);
    if ((t & 31) == 0) atomicAdd(&g_cnt[b], (int)p);
}

__global__ void valid_small(float* __restrict__ out_valid) {
    int b = threadIdx.x;
    if (b < NB) {
        float c = (float)g_cnt[b];
        out_valid[b] = (c >= 16384.0f * 0.05f && c <= 16384.0f * 0.95f) ? 1.0f : 0.0f;
    }
}

// ================= launch =================

extern "C" void kernel_launch(void* const* d_in, const int* in_sizes, int n_in,
                              void* d_out, int out_size) {
    const float* seg_masks   = (const float*)d_in[0];
    const float* cate_scores = (const float*)d_in[1];
    const float* feature_map = (const float*)d_in[2];
    const float* x           = (const float*)d_in[3];
    const float* targets     = (const float*)d_in[4];
    const int*   cate_labels = (const int*)d_in[5];

    float* out_scores = (float*)d_out;                  // [256]
    float* out_masks  = out_scores + NMS_N;             // [64*128*128]
    float* out_valid  = out_masks + NPIX;               // [64]

    // ---- NMS (also zeroes g_cnt) ----
    pack_kernel<<<NMS_N, 512>>>(seg_masks);
    nms_iou_kernel<<<NMS_N, NMS_N>>>(cate_labels);
    nms_coef_kernel<<<NMS_N, NMS_N>>>(cate_scores, out_scores);

    // ---- persistent CRF: weights + up to 10 iterations, exact early-exit ----
    cudaFuncSetAttribute(crf_persistent, cudaFuncAttributeMaxDynamicSharedMemorySize,
                         SMTOT * (int)sizeof(float));
    crf_persistent<<<2 * NB, 512, SMTOT * sizeof(float)>>>(feature_map, x, targets, out_masks);

    valid_small<<<1, 64>>>(out_valid);
}

// round 7
// speedup vs baseline: 1.6361x; 1.0907x over previous
#include <cuda_runtime.h>
#include <cuda_bf16.h>
#include <math.h>
#include <stdint.h>

// ---------------- problem sizes ----------------
#define NMS_N   256
#define HW      16384          // 128*128
#define WORDS   512            // 16384/32
#define NB      64             // batch for CRF
#define NPIX    (NB*HW)        // 1,048,576

// ---------------- persistent CRF config ----------------
#define CL      4              // cluster size (CTAs per image)
#define RPC     32             // rows per CTA
#define W136    136            // padded row stride (4 left, 4 right pad)
#define PLS     ((RPC+2)*W136) // state plane: top halo + RPC + bottom halo = 34 rows
#define SMTOT   (2*PLS + 8)    // two state planes + 8 flag slots

// ---------------- device scratch (static, no allocation) ----------------
__device__ unsigned int g_packed[NMS_N * WORDS];   // [mask][word]
__device__ float        g_sums[NMS_N];
__device__ float        g_dmat[NMS_N * NMS_N];
__device__ float        g_comp[NMS_N];
__device__ int          g_cnt[NB];

// ================= helpers =================

__device__ __forceinline__ void cluster_sync_() {
    asm volatile("barrier.cluster.arrive.aligned;" ::: "memory");
    asm volatile("barrier.cluster.wait.aligned;" ::: "memory");
}

__device__ __forceinline__ void st_peer_f32(uint32_t local_addr, uint32_t peer_rank, float v) {
    uint32_t rem;
    asm volatile("mapa.shared::cluster.u32 %0, %1, %2;"
                 : "=r"(rem) : "r"(local_addr), "r"(peer_rank));
    asm volatile("st.shared::cluster.f32 [%0], %1;" :: "r"(rem), "f"(v) : "memory");
}

// ================= NMS =================

__global__ void pack_kernel(const float* __restrict__ seg) {
    int m   = blockIdx.x;
    int tid = threadIdx.x;         // 512 threads
    int warp = tid >> 5, lane = tid & 31;
    if (blockIdx.x == 0 && tid < NB) g_cnt[tid] = 0;
    int cnt = 0;
    for (int w = warp; w < WORDS; w += 16) {
        float v = seg[(size_t)m * HW + w * 32 + lane];
        unsigned bal = __ballot_sync(0xffffffffu, v != 0.0f);
        if (lane == 0) {
            g_packed[m * WORDS + w] = bal;
            cnt += __popc(bal);
        }
    }
    __shared__ int scnt[16];
    if (lane == 0) scnt[warp] = cnt;
    __syncthreads();
    if (tid == 0) {
        int t = 0;
        for (int i = 0; i < 16; ++i) t += scnt[i];
        g_sums[m] = (float)t;
    }
}

__global__ void nms_iou_kernel(const int* __restrict__ labels) {
    int j = blockIdx.x;
    int i = threadIdx.x;
    __shared__ uint4 smj[WORDS / 4];
    if (i < WORDS / 4)
        smj[i] = ((const uint4*)(g_packed + (size_t)j * WORDS))[i];
    __syncthreads();

    float d = 0.0f;
    if (i < j && labels[i] == labels[j]) {
        const uint4* mi = (const uint4*)(g_packed + (size_t)i * WORDS);
        int inter = 0;
        #pragma unroll 8
        for (int w = 0; w < WORDS / 4; ++w) {
            uint4 a = mi[w];
            uint4 b = smj[w];
            inter += __popc(a.x & b.x) + __popc(a.y & b.y)
                   + __popc(a.z & b.z) + __popc(a.w & b.w);
        }
        float fi  = (float)inter;
        float uni = g_sums[j] + g_sums[i] - fi;
        d = fi / uni;
    }
    g_dmat[j * NMS_N + i] = d;

    __shared__ float red[NMS_N];
    red[i] = d;
    __syncthreads();
    for (int s = NMS_N / 2; s > 0; s >>= 1) {
        if (i < s) red[i] = fmaxf(red[i], red[i + s]);
        __syncthreads();
    }
    if (i == 0) g_comp[j] = red[0];
}

__global__ void nms_coef_kernel(const float* __restrict__ cate_scores,
                                float* __restrict__ out_scores) {
    int j = blockIdx.x;
    int i = threadIdx.x;
    float d  = g_dmat[j * NMS_N + i];
    float ci = g_comp[i];
    float v  = expf(-2.0f * d * d) / expf(-2.0f * ci * ci);
    __shared__ float red[NMS_N];
    red[i] = v;
    __syncthreads();
    for (int s = NMS_N / 2; s > 0; s >>= 1) {
        if (i < s) red[i] = fminf(red[i], red[i + s]);
        __syncthreads();
    }
    if (i == 0) out_scores[j] = cate_scores[j] * red[0];
}

// ================= persistent CRF =================
// Cluster of 4 CTAs per image, 32 rows each, 1024 threads, 4 px/thread.
// All 8 direction weights live in registers; smem holds only +-1 states.

__global__ void __cluster_dims__(CL, 1, 1) __launch_bounds__(1024, 1)
crf_persistent(const float* __restrict__ fm,
               const float* __restrict__ x, const float* __restrict__ tg,
               float* __restrict__ out_masks) {
    __shared__ float sm[SMTOT];
    float* st0  = sm;
    float* st1  = sm + PLS;
    float* flag = sm + 2 * PLS;    // [parity*4 + rank]

    int t  = threadIdx.x;          // 1024
    int b  = blockIdx.x >> 2;
    uint32_t r = blockIdx.x & 3;
    int tr = t >> 5;               // 0..31 local row
    int c  = (t & 31) << 2;        // 0..124 col base (4 px/thread)
    int gr = (int)r * RPC + tr;
    size_t gp = (size_t)b * HW + (size_t)gr * 128 + c;
    int so = (tr + 1) * W136 + 4 + c;

    for (int i = t; i < SMTOT; i += 1024) sm[i] = 0.0f;

    // ---- per-thread weights in registers (8 dirs x 4 px) ----
    const float* fb = fm + (size_t)b * 3 * HW;
    float wE[4], wW[4], wS[4], wN[4], wSE[4], wNW[4], wSW[4], wNE[4];
    {
        const int   dh[8] = { 0,  0,  1, -1,  1, -1,  1, -1};
        const int   dw[8] = { 1, -1,  0,  0,  1, -1, -1,  1};
        const float sp[8] = {1.0f/1800.0f, 1.0f/1800.0f, 1.0f/1800.0f, 1.0f/1800.0f,
                             2.0f/1800.0f, 2.0f/1800.0f, 2.0f/1800.0f, 2.0f/1800.0f};
        #pragma unroll
        for (int j = 0; j < 4; ++j) {
            int w = c + j;
            size_t pc = (size_t)gr * 128 + w;
            float c0 = fb[pc] + 10.0f;
            float c1 = fb[HW + pc] + 10.0f;
            float c2 = fb[2 * HW + pc] + 10.0f;
            float wv[8];
            #pragma unroll
            for (int d = 0; d < 8; ++d) {
                int hh = gr + dh[d], ww = w + dw[d];
                float v = 0.0f;
                if (hh >= 0 && hh < 128 && ww >= 0 && ww < 128) {
                    size_t pn = (size_t)hh * 128 + ww;
                    float d0 = (fb[pn] + 10.0f) - c0;
                    float d1 = (fb[HW + pn] + 10.0f) - c1;
                    float d2 = (fb[2 * HW + pn] + 10.0f) - c2;
                    float ss = d0 * d0 + d1 * d1 + d2 * d2;
                    v = 3.0f * expf(-ss * 2.0f - sp[d]);
                }
                wv[d] = v;
            }
            wE[j] = wv[0]; wW[j] = wv[1]; wS[j] = wv[2]; wN[j] = wv[3];
            wSE[j] = wv[4]; wNW[j] = wv[5]; wSW[j] = wv[6]; wNE[j] = wv[7];
        }
    }
    __syncthreads();   // smem zeroing complete before state writes

    // ---- init states (+-1) and target bits ----
    bool sndUp = (tr == 0)        && (r > 0);       // my row 0 -> rank r-1 bottom halo (row 33)
    bool sndDn = (tr == RPC - 1)  && (r < CL - 1);  // my row 31 -> rank r+1 top halo (row 0)
    unsigned tb = 0, prevmask = 0;
    {
        float4 xa = *(const float4*)(x + gp);
        float4 ta = *(const float4*)(tg + gp);
        float xs[4] = {xa.x, xa.y, xa.z, xa.w};
        float ts[4] = {ta.x, ta.y, ta.z, ta.w};
        float sig[4];
        #pragma unroll
        for (int i = 0; i < 4; ++i) {
            if (ts[i] > 0.5f) tb |= (1u << i);
            bool on = (xs[i] * ts[i] > 0.5f);
            if (on) prevmask |= (1u << i);
            sig[i] = on ? 1.0f : -1.0f;
        }
        *(float4*)(st0 + so) = make_float4(sig[0], sig[1], sig[2], sig[3]);
        if (sndUp) {
            uint32_t la = (uint32_t)__cvta_generic_to_shared(st0 + (RPC + 1) * W136 + 4 + c);
            #pragma unroll
            for (int i = 0; i < 4; ++i) st_peer_f32(la + 4u * i, r - 1u, sig[i]);
        }
        if (sndDn) {
            uint32_t la = (uint32_t)__cvta_generic_to_shared(st0 + 4 + c);
            #pragma unroll
            for (int i = 0; i < 4; ++i) st_peer_f32(la + 4u * i, r + 1u, sig[i]);
        }
    }
    uint32_t flag_base = (uint32_t)__cvta_generic_to_shared(flag);
    cluster_sync_();

    const float* A = st0;
    float* B = st1;
    unsigned newmask = prevmask;
    for (int it = 0; it < 10; ++it) {
        const float* Ar = A + so;
        float4 cu = *(const float4*)(Ar - W136);
        float4 cm = *(const float4*)(Ar);
        float4 cd = *(const float4*)(Ar + W136);
        float lu = Ar[-W136 - 1], ru = Ar[-W136 + 4];
        float lm = Ar[-1],        rm = Ar[4];
        float ld = Ar[W136 - 1],  rd = Ar[W136 + 4];
        float tw[6] = {lu, cu.x, cu.y, cu.z, cu.w, ru};
        float mw[6] = {lm, cm.x, cm.y, cm.z, cm.w, rm};
        float bw[6] = {ld, cd.x, cd.y, cd.z, cd.w, rd};

        newmask = 0;
        #pragma unroll
        for (int j = 0; j < 4; ++j) {
            float acc = 3.0f * mw[j + 1];
            acc += wE[j]  * mw[j + 2];
            acc += wW[j]  * mw[j];
            acc += wS[j]  * bw[j + 1];
            acc += wN[j]  * tw[j + 1];
            acc += wSE[j] * bw[j + 2];
            acc += wNW[j] * tw[j];
            acc += wSW[j] * bw[j];
            acc += wNE[j] * tw[j + 2];
            if (acc > 0.0f && ((tb >> j) & 1u)) newmask |= (1u << j);
        }

        int changed = (newmask != prevmask) ? 1 : 0;
        prevmask = newmask;
        int blkchg = __syncthreads_or(changed);
        if (it == 9) break;

        float sig[4];
        #pragma unroll
        for (int i = 0; i < 4; ++i)
            sig[i] = ((newmask >> i) & 1u) ? 1.0f : -1.0f;
        *(float4*)(B + so) = make_float4(sig[0], sig[1], sig[2], sig[3]);
        if (sndUp) {
            uint32_t la = (uint32_t)__cvta_generic_to_shared(B + (RPC + 1) * W136 + 4 + c);
            #pragma unroll
            for (int i = 0; i < 4; ++i) st_peer_f32(la + 4u * i, r - 1u, sig[i]);
        }
        if (sndDn) {
            uint32_t la = (uint32_t)__cvta_generic_to_shared(B + 4 + c);
            #pragma unroll
            for (int i = 0; i < 4; ++i) st_peer_f32(la + 4u * i, r + 1u, sig[i]);
        }
        if (t == 0) {
            float fv = blkchg ? 1.0f : 0.0f;
            uint32_t slot = flag_base + 4u * ((unsigned)(it & 1) * 4u + r);
            #pragma unroll
            for (uint32_t rr = 0; rr < CL; ++rr) st_peer_f32(slot, rr, fv);
        }
        cluster_sync_();
        int p4 = (it & 1) * 4;
        bool anychg = (flag[p4] != 0.0f) || (flag[p4 + 1] != 0.0f) ||
                      (flag[p4 + 2] != 0.0f) || (flag[p4 + 3] != 0.0f);
        if (!anychg) break;   // exact fixed point across the whole image
        const float* tmp = A; A = B; B = (float*)tmp;
    }

    // ---- final outputs ----
    float o[4];
    #pragma unroll
    for (int i = 0; i < 4; ++i) o[i] = ((newmask >> i) & 1u) ? 1.0f : 0.0f;
    *(float4*)(out_masks + gp) = make_float4(o[0], o[1], o[2], o[3]);

    unsigned p = __popc(newmask);
    #pragma unroll
    for (int off = 16; off; off >>= 1) p += __shfl_down_sync(0xffffffffu, p, off);
    if ((t & 31) == 0) atomicAdd(&g_cnt[b], (int)p);
}

__global__ void valid_small(float* __restrict__ out_valid) {
    int b = threadIdx.x;
    if (b < NB) {
        float c = (float)g_cnt[b];
        out_valid[b] = (c >= 16384.0f * 0.05f && c <= 16384.0f * 0.95f) ? 1.0f : 0.0f;
    }
}

// ================= launch =================

extern "C" void kernel_launch(void* const* d_in, const int* in_sizes, int n_in,
                              void* d_out, int out_size) {
    const float* seg_masks   = (const float*)d_in[0];
    const float* cate_scores = (const float*)d_in[1];
    const float* feature_map = (const float*)d_in[2];
    const float* x           = (const float*)d_in[3];
    const float* targets     = (const float*)d_in[4];
    const int*   cate_labels = (const int*)d_in[5];

    float* out_scores = (float*)d_out;                  // [256]
    float* out_masks  = out_scores + NMS_N;             // [64*128*128]
    float* out_valid  = out_masks + NPIX;               // [64]

    // ---- NMS (also zeroes g_cnt) ----
    pack_kernel<<<NMS_N, 512>>>(seg_masks);
    nms_iou_kernel<<<NMS_N, NMS_N>>>(cate_labels);
    nms_coef_kernel<<<NMS_N, NMS_N>>>(cate_scores, out_scores);

    // ---- persistent CRF: weights in registers, states in smem ----
    crf_persistent<<<CL * NB, 1024>>>(feature_map, x, targets, out_masks);

    valid_small<<<1, 64>>>(out_valid);
}

// round 8
// speedup vs baseline: 1.6869x; 1.0310x over previous
#include <cuda_runtime.h>
#include <cuda_bf16.h>
#include <math.h>
#include <stdint.h>

// ---------------- problem sizes ----------------
#define NMS_N   256
#define HW      16384          // 128*128
#define WORDS   512            // 16384/32
#define NB      64             // batch for CRF
#define NPIX    (NB*HW)        // 1,048,576

// ---------------- persistent CRF config ----------------
#define CL      4              // cluster size (CTAs per image)
#define RPC     32             // rows per CTA
#define W136    136            // padded row stride (4 left, 4 right pad)
#define PLS     ((RPC+2)*W136) // state plane: halo + RPC + halo
#define SMTOT   (2*PLS + 8)

// ---------------- device scratch (static, no allocation) ----------------
__device__ unsigned int g_packed[NMS_N * WORDS];   // [mask][word]
__device__ float        g_sums[NMS_N];
__device__ float        g_dmat[NMS_N * NMS_N];
__device__ float        g_comp[NMS_N];
__device__ int          g_cnt[NB];

// ================= helpers =================

__device__ __forceinline__ void cluster_sync_() {
    asm volatile("barrier.cluster.arrive.aligned;" ::: "memory");
    asm volatile("barrier.cluster.wait.aligned;" ::: "memory");
}

__device__ __forceinline__ void st_peer_f32(uint32_t local_addr, uint32_t peer_rank, float v) {
    uint32_t rem;
    asm volatile("mapa.shared::cluster.u32 %0, %1, %2;"
                 : "=r"(rem) : "r"(local_addr), "r"(peer_rank));
    asm volatile("st.shared::cluster.f32 [%0], %1;" :: "r"(rem), "f"(v) : "memory");
}

// ================= NMS =================

__global__ void pack_kernel(const float* __restrict__ seg) {
    int m   = blockIdx.x;
    int tid = threadIdx.x;         // 512 threads
    int warp = tid >> 5, lane = tid & 31;
    if (blockIdx.x == 0 && tid < NB) g_cnt[tid] = 0;
    int cnt = 0;
    for (int w = warp; w < WORDS; w += 16) {
        float v = seg[(size_t)m * HW + w * 32 + lane];
        unsigned bal = __ballot_sync(0xffffffffu, v != 0.0f);
        if (lane == 0) {
            g_packed[m * WORDS + w] = bal;
            cnt += __popc(bal);
        }
    }
    __shared__ int scnt[16];
    if (lane == 0) scnt[warp] = cnt;
    __syncthreads();
    if (tid == 0) {
        int t = 0;
        for (int i = 0; i < 16; ++i) t += scnt[i];
        g_sums[m] = (float)t;
    }
}

__global__ void nms_iou_kernel(const int* __restrict__ labels) {
    int j = blockIdx.x;
    int i = threadIdx.x;
    __shared__ uint4 smj[WORDS / 4];
    if (i < WORDS / 4)
        smj[i] = ((const uint4*)(g_packed + (size_t)j * WORDS))[i];
    __syncthreads();

    float d = 0.0f;
    if (i < j && labels[i] == labels[j]) {
        const uint4* mi = (const uint4*)(g_packed + (size_t)i * WORDS);
        int inter = 0;
        #pragma unroll 8
        for (int w = 0; w < WORDS / 4; ++w) {
            uint4 a = mi[w];
            uint4 b = smj[w];
            inter += __popc(a.x & b.x) + __popc(a.y & b.y)
                   + __popc(a.z & b.z) + __popc(a.w & b.w);
        }
        float fi  = (float)inter;
        float uni = g_sums[j] + g_sums[i] - fi;
        d = fi / uni;
    }
    g_dmat[j * NMS_N + i] = d;

    __shared__ float red[NMS_N];
    red[i] = d;
    __syncthreads();
    for (int s = NMS_N / 2; s > 0; s >>= 1) {
        if (i < s) red[i] = fmaxf(red[i], red[i + s]);
        __syncthreads();
    }
    if (i == 0) g_comp[j] = red[0];
}

__global__ void nms_coef_kernel(const float* __restrict__ cate_scores,
                                float* __restrict__ out_scores) {
    int j = blockIdx.x;
    int i = threadIdx.x;
    float d  = g_dmat[j * NMS_N + i];
    float ci = g_comp[i];
    float v  = expf(-2.0f * d * d) / expf(-2.0f * ci * ci);
    __shared__ float red[NMS_N];
    red[i] = v;
    __syncthreads();
    for (int s = NMS_N / 2; s > 0; s >>= 1) {
        if (i < s) red[i] = fminf(red[i], red[i + s]);
        __syncthreads();
    }
    if (i == 0) out_scores[j] = cate_scores[j] * red[0];
}

// ================= persistent CRF =================
// Cluster of 4 CTAs per image, 32 rows each, 1024 threads, 4 px/thread.
// Weights in registers (kept live, small loop working set -> no spills);
// smem holds only +-1 states.

__global__ void __cluster_dims__(CL, 1, 1) __launch_bounds__(1024, 1)
crf_persistent(const float* __restrict__ fm,
               const float* __restrict__ x, const float* __restrict__ tg,
               float* __restrict__ out_masks) {
    __shared__ float sm[SMTOT];
    float* st0  = sm;
    float* st1  = sm + PLS;
    float* flag = sm + 2 * PLS;    // [parity*4 + rank]

    int t  = threadIdx.x;          // 1024
    int b  = blockIdx.x >> 2;
    uint32_t r = blockIdx.x & 3;
    int tr = t >> 5;               // 0..31 local row
    int c  = (t & 31) << 2;        // 0..124 col base
    int gr = (int)r * RPC + tr;
    size_t gp = (size_t)b * HW + (size_t)gr * 128 + c;
    int so = (tr + 1) * W136 + 4 + c;

    for (int i = t; i < SMTOT; i += 1024) sm[i] = 0.0f;

    // ---- weights in registers, grouped by stencil row ----
    // top row dirs: N, NW, NE ; mid: E, W ; bottom: S, SE, SW
    float wN[4], wNW[4], wNE[4], wE[4], wW[4], wS[4], wSE[4], wSW[4];
    {
        const float* fb = fm + (size_t)b * 3 * HW;
        // ss accumulators, same grouping
        float sN[4], sNW[4], sNE[4], sE[4], sW[4], sS[4], sSE[4], sSW[4];
        #pragma unroll
        for (int ch = 0; ch < 3; ++ch) {
            const float* base = fb + (size_t)ch * HW;
            float w6[3][6];    // rows gr-1,gr,gr+1 ; cols c-1..c+4 (+10 applied)
            #pragma unroll
            for (int rr = 0; rr < 3; ++rr) {
                int row = gr - 1 + rr;
                bool rin = (row >= 0) && (row < 128);
                size_t rp = (size_t)(rin ? row : gr) * 128 + c;
                float4 v = *(const float4*)(base + rp);
                float lf = (c > 0)   ? base[rp - 1] : 0.0f;
                float rt = (c < 124) ? base[rp + 4] : 0.0f;
                if (!rin) { v = make_float4(0,0,0,0); lf = 0.0f; rt = 0.0f; }
                w6[rr][0] = lf  + 10.0f;
                w6[rr][1] = v.x + 10.0f;
                w6[rr][2] = v.y + 10.0f;
                w6[rr][3] = v.z + 10.0f;
                w6[rr][4] = v.w + 10.0f;
                w6[rr][5] = rt  + 10.0f;
            }
            #pragma unroll
            for (int j = 0; j < 4; ++j) {
                float cc = w6[1][1 + j];
                float dN  = w6[0][1 + j] - cc;
                float dNW = w6[0][j]     - cc;
                float dNE = w6[0][2 + j] - cc;
                float dE  = w6[1][2 + j] - cc;
                float dW  = w6[1][j]     - cc;
                float dS  = w6[2][1 + j] - cc;
                float dSE = w6[2][2 + j] - cc;
                float dSW = w6[2][j]     - cc;
                if (ch == 0) {
                    sN[j]=dN*dN; sNW[j]=dNW*dNW; sNE[j]=dNE*dNE;
                    sE[j]=dE*dE; sW[j]=dW*dW;
                    sS[j]=dS*dS; sSE[j]=dSE*dSE; sSW[j]=dSW*dSW;
                } else {
                    sN[j]=fmaf(dN,dN,sN[j]);   sNW[j]=fmaf(dNW,dNW,sNW[j]);
                    sNE[j]=fmaf(dNE,dNE,sNE[j]); sE[j]=fmaf(dE,dE,sE[j]);
                    sW[j]=fmaf(dW,dW,sW[j]);   sS[j]=fmaf(dS,dS,sS[j]);
                    sSE[j]=fmaf(dSE,dSE,sSE[j]); sSW[j]=fmaf(dSW,dSW,sSW[j]);
                }
            }
        }
        const float sp1 = 1.0f / 1800.0f;   // axis dirs
        const float sp2 = 2.0f / 1800.0f;   // diagonal dirs
        bool hT = (gr > 0), hB = (gr < 127);
        #pragma unroll
        for (int j = 0; j < 4; ++j) {
            int w = c + j;
            bool hL = (w > 0), hR = (w < 127);
            float ss, v;
            ss = sN[j];  v = 3.0f * expf(-ss * 2.0f - sp1); wN[j]  = hT        ? v : 0.0f;
            ss = sNW[j]; v = 3.0f * expf(-ss * 2.0f - sp2); wNW[j] = (hT && hL)? v : 0.0f;
            ss = sNE[j]; v = 3.0f * expf(-ss * 2.0f - sp2); wNE[j] = (hT && hR)? v : 0.0f;
            ss = sE[j];  v = 3.0f * expf(-ss * 2.0f - sp1); wE[j]  = hR        ? v : 0.0f;
            ss = sW[j];  v = 3.0f * expf(-ss * 2.0f - sp1); wW[j]  = hL        ? v : 0.0f;
            ss = sS[j];  v = 3.0f * expf(-ss * 2.0f - sp1); wS[j]  = hB        ? v : 0.0f;
            ss = sSE[j]; v = 3.0f * expf(-ss * 2.0f - sp2); wSE[j] = (hB && hR)? v : 0.0f;
            ss = sSW[j]; v = 3.0f * expf(-ss * 2.0f - sp2); wSW[j] = (hB && hL)? v : 0.0f;
        }
    }
    __syncthreads();   // smem zeroing complete before state writes

    // ---- init states (+-1) and target bits ----
    bool sndUp = (tr == 0)       && (r > 0);
    bool sndDn = (tr == RPC - 1) && (r < CL - 1);
    unsigned tb = 0, prevmask = 0;
    {
        float4 xa = *(const float4*)(x + gp);
        float4 ta = *(const float4*)(tg + gp);
        float xs[4] = {xa.x, xa.y, xa.z, xa.w};
        float ts[4] = {ta.x, ta.y, ta.z, ta.w};
        float sig[4];
        #pragma unroll
        for (int i = 0; i < 4; ++i) {
            if (ts[i] > 0.5f) tb |= (1u << i);
            bool on = (xs[i] * ts[i] > 0.5f);
            if (on) prevmask |= (1u << i);
            sig[i] = on ? 1.0f : -1.0f;
        }
        *(float4*)(st0 + so) = make_float4(sig[0], sig[1], sig[2], sig[3]);
        if (sndUp) {
            uint32_t la = (uint32_t)__cvta_generic_to_shared(st0 + (RPC + 1) * W136 + 4 + c);
            #pragma unroll
            for (int i = 0; i < 4; ++i) st_peer_f32(la + 4u * i, r - 1u, sig[i]);
        }
        if (sndDn) {
            uint32_t la = (uint32_t)__cvta_generic_to_shared(st0 + 4 + c);
            #pragma unroll
            for (int i = 0; i < 4; ++i) st_peer_f32(la + 4u * i, r + 1u, sig[i]);
        }
    }
    uint32_t flag_base = (uint32_t)__cvta_generic_to_shared(flag);
    cluster_sync_();

    const float* A = st0;
    float* B = st1;
    unsigned newmask = prevmask;
    for (int it = 0; it < 10; ++it) {
        const float* Ar = A + so;
        float acc[4];
        {   // mid row: center + E + W
            float4 m4 = *(const float4*)(Ar);
            float lm = Ar[-1], rm = Ar[4];
            float mw[6] = {lm, m4.x, m4.y, m4.z, m4.w, rm};
            #pragma unroll
            for (int j = 0; j < 4; ++j) {
                float a = 3.0f * mw[j + 1];
                a += wE[j] * mw[j + 2];
                a += wW[j] * mw[j];
                acc[j] = a;
            }
        }
        {   // top row: N + NW + NE
            float4 u4 = *(const float4*)(Ar - W136);
            float lu = Ar[-W136 - 1], ru = Ar[-W136 + 4];
            float tw[6] = {lu, u4.x, u4.y, u4.z, u4.w, ru};
            #pragma unroll
            for (int j = 0; j < 4; ++j) {
                float a = acc[j];
                a += wN[j]  * tw[j + 1];
                a += wNW[j] * tw[j];
                a += wNE[j] * tw[j + 2];
                acc[j] = a;
            }
        }
        {   // bottom row: S + SE + SW
            float4 d4 = *(const float4*)(Ar + W136);
            float ld = Ar[W136 - 1], rd = Ar[W136 + 4];
            float bw[6] = {ld, d4.x, d4.y, d4.z, d4.w, rd};
            #pragma unroll
            for (int j = 0; j < 4; ++j) {
                float a = acc[j];
                a += wS[j]  * bw[j + 1];
                a += wSE[j] * bw[j + 2];
                a += wSW[j] * bw[j];
                acc[j] = a;
            }
        }
        newmask = 0;
        #pragma unroll
        for (int j = 0; j < 4; ++j)
            if (acc[j] > 0.0f && ((tb >> j) & 1u)) newmask |= (1u << j);

        int changed = (newmask != prevmask) ? 1 : 0;
        prevmask = newmask;
        int blkchg = __syncthreads_or(changed);
        if (it == 9) break;

        float sig[4];
        #pragma unroll
        for (int i = 0; i < 4; ++i)
            sig[i] = ((newmask >> i) & 1u) ? 1.0f : -1.0f;
        *(float4*)(B + so) = make_float4(sig[0], sig[1], sig[2], sig[3]);
        if (sndUp) {
            uint32_t la = (uint32_t)__cvta_generic_to_shared(B + (RPC + 1) * W136 + 4 + c);
            #pragma unroll
            for (int i = 0; i < 4; ++i) st_peer_f32(la + 4u * i, r - 1u, sig[i]);
        }
        if (sndDn) {
            uint32_t la = (uint32_t)__cvta_generic_to_shared(B + 4 + c);
            #pragma unroll
            for (int i = 0; i < 4; ++i) st_peer_f32(la + 4u * i, r + 1u, sig[i]);
        }
        if (t == 0) {
            float fv = blkchg ? 1.0f : 0.0f;
            uint32_t slot = flag_base + 4u * ((unsigned)(it & 1) * 4u + r);
            #pragma unroll
            for (uint32_t rr = 0; rr < CL; ++rr) st_peer_f32(slot, rr, fv);
        }
        cluster_sync_();
        int p4 = (it & 1) * 4;
        bool anychg = (flag[p4] != 0.0f) || (flag[p4 + 1] != 0.0f) ||
                      (flag[p4 + 2] != 0.0f) || (flag[p4 + 3] != 0.0f);
        if (!anychg) break;   // exact fixed point across the whole image
        const float* tmp = A; A = B; B = (float*)tmp;
    }

    // ---- final outputs ----
    float o[4];
    #pragma unroll
    for (int i = 0; i < 4; ++i) o[i] = ((newmask >> i) & 1u) ? 1.0f : 0.0f;
    *(float4*)(out_masks + gp) = make_float4(o[0], o[1], o[2], o[3]);

    unsigned p = __popc(newmask);
    #pragma unroll
    for (int off = 16; off; off >>= 1) p += __shfl_down_sync(0xffffffffu, p, off);
    if ((t & 31) == 0) atomicAdd(&g_cnt[b], (int)p);
}

__global__ void valid_small(float* __restrict__ out_valid) {
    int b = threadIdx.x;
    if (b < NB) {
        float c = (float)g_cnt[b];
        out_valid[b] = (c >= 16384.0f * 0.05f && c <= 16384.0f * 0.95f) ? 1.0f : 0.0f;
    }
}

// ================= launch =================

extern "C" void kernel_launch(void* const* d_in, const int* in_sizes, int n_in,
                              void* d_out, int out_size) {
    const float* seg_masks   = (const float*)d_in[0];
    const float* cate_scores = (const float*)d_in[1];
    const float* feature_map = (const float*)d_in[2];
    const float* x           = (const float*)d_in[3];
    const float* targets     = (const float*)d_in[4];
    const int*   cate_labels = (const int*)d_in[5];

    float* out_scores = (float*)d_out;                  // [256]
    float* out_masks  = out_scores + NMS_N;             // [64*128*128]
    float* out_valid  = out_masks + NPIX;               // [64]

    // ---- NMS (also zeroes g_cnt) ----
    pack_kernel<<<NMS_N, 512>>>(seg_masks);
    nms_iou_kernel<<<NMS_N, NMS_N>>>(cate_labels);
    nms_coef_kernel<<<NMS_N, NMS_N>>>(cate_scores, out_scores);

    // ---- persistent CRF ----
    crf_persistent<<<CL * NB, 1024>>>(feature_map, x, targets, out_masks);

    valid_small<<<1, 64>>>(out_valid);
}

// round 9
// speedup vs baseline: 2.3609x; 1.3996x over previous
#include <cuda_runtime.h>
#include <cuda_bf16.h>
#include <math.h>
#include <stdint.h>

// ---------------- problem sizes ----------------
#define NMS_N   256
#define HW      16384          // 128*128
#define WORDS   512            // 16384/32
#define NB      64             // batch for CRF
#define NPIX    (NB*HW)        // 1,048,576

// ---------------- persistent CRF config ----------------
#define CL      4              // cluster size (CTAs per image)
#define RPC     32             // rows per CTA
#define W136    136            // padded row stride (4 left, 4 right pad)
#define PLS     ((RPC+2)*W136) // state plane: halo + RPC + halo
#define SMTOT   (2*PLS + 8)

// ---------------- device scratch (static, no allocation) ----------------
__device__ unsigned int g_packed[NMS_N * WORDS];   // [mask][word]
__device__ float        g_sums[NMS_N];
__device__ float        g_dmat[NMS_N * NMS_N];
__device__ float        g_comp[NMS_N];
__device__ int          g_cnt[NB];                 // count | (arrivals<<20)

// ================= helpers =================

__device__ __forceinline__ void cluster_sync_() {
    asm volatile("barrier.cluster.arrive.aligned;" ::: "memory");
    asm volatile("barrier.cluster.wait.aligned;" ::: "memory");
}

__device__ __forceinline__ void st_peer_f32(uint32_t local_addr, uint32_t peer_rank, float v) {
    uint32_t rem;
    asm volatile("mapa.shared::cluster.u32 %0, %1, %2;"
                 : "=r"(rem) : "r"(local_addr), "r"(peer_rank));
    asm volatile("st.shared::cluster.f32 [%0], %1;" :: "r"(rem), "f"(v) : "memory");
}

// ================= NMS =================

__global__ void pack_kernel(const float* __restrict__ seg) {
    int m   = blockIdx.x;
    int tid = threadIdx.x;         // 512 threads
    int warp = tid >> 5, lane = tid & 31;
    int cnt = 0;
    for (int w = warp; w < WORDS; w += 16) {
        float v = seg[(size_t)m * HW + w * 32 + lane];
        unsigned bal = __ballot_sync(0xffffffffu, v != 0.0f);
        if (lane == 0) {
            g_packed[m * WORDS + w] = bal;
            cnt += __popc(bal);
        }
    }
    __shared__ int scnt[16];
    if (lane == 0) scnt[warp] = cnt;
    __syncthreads();
    if (tid == 0) {
        int t = 0;
        for (int i = 0; i < 16; ++i) t += scnt[i];
        g_sums[m] = (float)t;
    }
}

__global__ void nms_iou_kernel(const int* __restrict__ labels) {
    int j = blockIdx.x;
    int i = threadIdx.x;
    __shared__ uint4 smj[WORDS / 4];
    if (i < WORDS / 4)
        smj[i] = ((const uint4*)(g_packed + (size_t)j * WORDS))[i];
    __syncthreads();

    float d = 0.0f;
    if (i < j && labels[i] == labels[j]) {
        const uint4* mi = (const uint4*)(g_packed + (size_t)i * WORDS);
        int inter = 0;
        #pragma unroll 8
        for (int w = 0; w < WORDS / 4; ++w) {
            uint4 a = mi[w];
            uint4 b = smj[w];
            inter += __popc(a.x & b.x) + __popc(a.y & b.y)
                   + __popc(a.z & b.z) + __popc(a.w & b.w);
        }
        float fi  = (float)inter;
        float uni = g_sums[j] + g_sums[i] - fi;
        d = fi / uni;
    }
    g_dmat[j * NMS_N + i] = d;

    __shared__ float red[NMS_N];
    red[i] = d;
    __syncthreads();
    for (int s = NMS_N / 2; s > 0; s >>= 1) {
        if (i < s) red[i] = fmaxf(red[i], red[i + s]);
        __syncthreads();
    }
    if (i == 0) g_comp[j] = red[0];
}

__global__ void nms_coef_kernel(const float* __restrict__ cate_scores,
                                float* __restrict__ out_scores) {
    int j = blockIdx.x;
    int i = threadIdx.x;
    float d  = g_dmat[j * NMS_N + i];
    float ci = g_comp[i];
    float v  = expf(-2.0f * d * d) / expf(-2.0f * ci * ci);
    __shared__ float red[NMS_N];
    red[i] = v;
    __syncthreads();
    for (int s = NMS_N / 2; s > 0; s >>= 1) {
        if (i < s) red[i] = fminf(red[i], red[i + s]);
        __syncthreads();
    }
    if (i == 0) out_scores[j] = cate_scores[j] * red[0];
}

// ================= persistent CRF (+ fused valid) =================
// Cluster of 4 CTAs per image, 32 rows each, 1024 threads, 4 px/thread.
// Weights register-resident; smem holds only +-1 states.

__global__ void __cluster_dims__(CL, 1, 1) __launch_bounds__(1024, 1)
crf_persistent(const float* __restrict__ fm,
               const float* __restrict__ x, const float* __restrict__ tg,
               float* __restrict__ out_masks, float* __restrict__ out_valid) {
    __shared__ float sm[SMTOT];
    __shared__ int   red2[32];
    float* st0  = sm;
    float* st1  = sm + PLS;
    float* flag = sm + 2 * PLS;    // [parity*4 + rank]

    int t  = threadIdx.x;          // 1024
    int b  = blockIdx.x >> 2;
    uint32_t r = blockIdx.x & 3;
    int tr = t >> 5;               // 0..31 local row
    int c  = (t & 31) << 2;        // 0..124 col base
    int gr = (int)r * RPC + tr;
    size_t gp = (size_t)b * HW + (size_t)gr * 128 + c;
    int so = (tr + 1) * W136 + 4 + c;

    for (int i = t; i < SMTOT; i += 1024) sm[i] = 0.0f;

    if (r == 0 && t == 0) {        // reset per-image counter every launch (graph replay safe)
        g_cnt[b] = 0;
        __threadfence();
    }

    // ---- weights in registers, grouped by stencil row ----
    float wN[4], wNW[4], wNE[4], wE[4], wW[4], wS[4], wSE[4], wSW[4];
    {
        const float* fb = fm + (size_t)b * 3 * HW;
        float sN[4], sNW[4], sNE[4], sE[4], sW[4], sS[4], sSE[4], sSW[4];
        #pragma unroll
        for (int ch = 0; ch < 3; ++ch) {
            const float* base = fb + (size_t)ch * HW;
            float w6[3][6];
            #pragma unroll
            for (int rr = 0; rr < 3; ++rr) {
                int row = gr - 1 + rr;
                bool rin = (row >= 0) && (row < 128);
                size_t rp = (size_t)(rin ? row : gr) * 128 + c;
                float4 v = *(const float4*)(base + rp);
                float lf = (c > 0)   ? base[rp - 1] : 0.0f;
                float rt = (c < 124) ? base[rp + 4] : 0.0f;
                if (!rin) { v = make_float4(0,0,0,0); lf = 0.0f; rt = 0.0f; }
                w6[rr][0] = lf  + 10.0f;
                w6[rr][1] = v.x + 10.0f;
                w6[rr][2] = v.y + 10.0f;
                w6[rr][3] = v.z + 10.0f;
                w6[rr][4] = v.w + 10.0f;
                w6[rr][5] = rt  + 10.0f;
            }
            #pragma unroll
            for (int j = 0; j < 4; ++j) {
                float cc = w6[1][1 + j];
                float dN  = w6[0][1 + j] - cc;
                float dNW = w6[0][j]     - cc;
                float dNE = w6[0][2 + j] - cc;
                float dE  = w6[1][2 + j] - cc;
                float dW  = w6[1][j]     - cc;
                float dS  = w6[2][1 + j] - cc;
                float dSE = w6[2][2 + j] - cc;
                float dSW = w6[2][j]     - cc;
                if (ch == 0) {
                    sN[j]=dN*dN; sNW[j]=dNW*dNW; sNE[j]=dNE*dNE;
                    sE[j]=dE*dE; sW[j]=dW*dW;
                    sS[j]=dS*dS; sSE[j]=dSE*dSE; sSW[j]=dSW*dSW;
                } else {
                    sN[j]=fmaf(dN,dN,sN[j]);    sNW[j]=fmaf(dNW,dNW,sNW[j]);
                    sNE[j]=fmaf(dNE,dNE,sNE[j]); sE[j]=fmaf(dE,dE,sE[j]);
                    sW[j]=fmaf(dW,dW,sW[j]);    sS[j]=fmaf(dS,dS,sS[j]);
                    sSE[j]=fmaf(dSE,dSE,sSE[j]); sSW[j]=fmaf(dSW,dSW,sSW[j]);
                }
            }
        }
        const float sp1 = 1.0f / 1800.0f;
        const float sp2 = 2.0f / 1800.0f;
        bool hT = (gr > 0), hB = (gr < 127);
        #pragma unroll
        for (int j = 0; j < 4; ++j) {
            int w = c + j;
            bool hL = (w > 0), hR = (w < 127);
            float ss, v;
            ss = sN[j];  v = 3.0f * expf(-ss * 2.0f - sp1); wN[j]  = hT        ? v : 0.0f;
            ss = sNW[j]; v = 3.0f * expf(-ss * 2.0f - sp2); wNW[j] = (hT && hL)? v : 0.0f;
            ss = sNE[j]; v = 3.0f * expf(-ss * 2.0f - sp2); wNE[j] = (hT && hR)? v : 0.0f;
            ss = sE[j];  v = 3.0f * expf(-ss * 2.0f - sp1); wE[j]  = hR        ? v : 0.0f;
            ss = sW[j];  v = 3.0f * expf(-ss * 2.0f - sp1); wW[j]  = hL        ? v : 0.0f;
            ss = sS[j];  v = 3.0f * expf(-ss * 2.0f - sp1); wS[j]  = hB        ? v : 0.0f;
            ss = sSE[j]; v = 3.0f * expf(-ss * 2.0f - sp2); wSE[j] = (hB && hR)? v : 0.0f;
            ss = sSW[j]; v = 3.0f * expf(-ss * 2.0f - sp2); wSW[j] = (hB && hL)? v : 0.0f;
        }
    }
    __syncthreads();   // smem zeroing complete before state writes

    // ---- init states (+-1) and target bits ----
    bool sndUp = (tr == 0)       && (r > 0);
    bool sndDn = (tr == RPC - 1) && (r < CL - 1);
    unsigned tb = 0, prevmask = 0;
    {
        float4 xa = *(const float4*)(x + gp);
        float4 ta = *(const float4*)(tg + gp);
        float xs[4] = {xa.x, xa.y, xa.z, xa.w};
        float ts[4] = {ta.x, ta.y, ta.z, ta.w};
        float sig[4];
        #pragma unroll
        for (int i = 0; i < 4; ++i) {
            if (ts[i] > 0.5f) tb |= (1u << i);
            bool on = (xs[i] * ts[i] > 0.5f);
            if (on) prevmask |= (1u << i);
            sig[i] = on ? 1.0f : -1.0f;
        }
        *(float4*)(st0 + so) = make_float4(sig[0], sig[1], sig[2], sig[3]);
        if (sndUp) {
            uint32_t la = (uint32_t)__cvta_generic_to_shared(st0 + (RPC + 1) * W136 + 4 + c);
            #pragma unroll
            for (int i = 0; i < 4; ++i) st_peer_f32(la + 4u * i, r - 1u, sig[i]);
        }
        if (sndDn) {
            uint32_t la = (uint32_t)__cvta_generic_to_shared(st0 + 4 + c);
            #pragma unroll
            for (int i = 0; i < 4; ++i) st_peer_f32(la + 4u * i, r + 1u, sig[i]);
        }
    }
    uint32_t flag_base = (uint32_t)__cvta_generic_to_shared(flag);
    cluster_sync_();

    const float* A = st0;
    float* B = st1;
    unsigned newmask = prevmask;
    for (int it = 0; it < 10; ++it) {
        const float* Ar = A + so;
        float acc[4];
        {   // mid row: center + E + W
            float4 m4 = *(const float4*)(Ar);
            float lm = Ar[-1], rm = Ar[4];
            float mw[6] = {lm, m4.x, m4.y, m4.z, m4.w, rm};
            #pragma unroll
            for (int j = 0; j < 4; ++j) {
                float a = 3.0f * mw[j + 1];
                a += wE[j] * mw[j + 2];
                a += wW[j] * mw[j];
                acc[j] = a;
            }
        }
        {   // top row: N + NW + NE
            float4 u4 = *(const float4*)(Ar - W136);
            float lu = Ar[-W136 - 1], ru = Ar[-W136 + 4];
            float tw[6] = {lu, u4.x, u4.y, u4.z, u4.w, ru};
            #pragma unroll
            for (int j = 0; j < 4; ++j) {
                float a = acc[j];
                a += wN[j]  * tw[j + 1];
                a += wNW[j] * tw[j];
                a += wNE[j] * tw[j + 2];
                acc[j] = a;
            }
        }
        {   // bottom row: S + SE + SW
            float4 d4 = *(const float4*)(Ar + W136);
            float ld = Ar[W136 - 1], rd = Ar[W136 + 4];
            float bw[6] = {ld, d4.x, d4.y, d4.z, d4.w, rd};
            #pragma unroll
            for (int j = 0; j < 4; ++j) {
                float a = acc[j];
                a += wS[j]  * bw[j + 1];
                a += wSE[j] * bw[j + 2];
                a += wSW[j] * bw[j];
                acc[j] = a;
            }
        }
        newmask = 0;
        #pragma unroll
        for (int j = 0; j < 4; ++j)
            if (acc[j] > 0.0f && ((tb >> j) & 1u)) newmask |= (1u << j);

        int changed = (newmask != prevmask) ? 1 : 0;
        prevmask = newmask;
        int blkchg = __syncthreads_or(changed);
        if (it == 9) break;

        float sig[4];
        #pragma unroll
        for (int i = 0; i < 4; ++i)
            sig[i] = ((newmask >> i) & 1u) ? 1.0f : -1.0f;
        *(float4*)(B + so) = make_float4(sig[0], sig[1], sig[2], sig[3]);
        if (sndUp) {
            uint32_t la = (uint32_t)__cvta_generic_to_shared(B + (RPC + 1) * W136 + 4 + c);
            #pragma unroll
            for (int i = 0; i < 4; ++i) st_peer_f32(la + 4u * i, r - 1u, sig[i]);
        }
        if (sndDn) {
            uint32_t la = (uint32_t)__cvta_generic_to_shared(B + 4 + c);
            #pragma unroll
            for (int i = 0; i < 4; ++i) st_peer_f32(la + 4u * i, r + 1u, sig[i]);
        }
        if (t == 0) {
            float fv = blkchg ? 1.0f : 0.0f;
            uint32_t slot = flag_base + 4u * ((unsigned)(it & 1) * 4u + r);
            #pragma unroll
            for (uint32_t rr = 0; rr < CL; ++rr) st_peer_f32(slot, rr, fv);
        }
        cluster_sync_();
        int p4 = (it & 1) * 4;
        bool anychg = (flag[p4] != 0.0f) || (flag[p4 + 1] != 0.0f) ||
                      (flag[p4 + 2] != 0.0f) || (flag[p4 + 3] != 0.0f);
        if (!anychg) break;   // exact fixed point across the whole image
        const float* tmp = A; A = B; B = (float*)tmp;
    }

    // ---- final outputs ----
    float o[4];
    #pragma unroll
    for (int i = 0; i < 4; ++i) o[i] = ((newmask >> i) & 1u) ? 1.0f : 0.0f;
    *(float4*)(out_masks + gp) = make_float4(o[0], o[1], o[2], o[3]);

    // ---- fused valid: block reduce popcount, combined atomic, last CTA writes ----
    unsigned p = __popc(newmask);
    #pragma unroll
    for (int off = 16; off; off >>= 1) p += __shfl_down_sync(0xffffffffu, p, off);
    if ((t & 31) == 0) red2[t >> 5] = (int)p;
    __syncthreads();
    if (t < 32) {
        int v = red2[t];
        #pragma unroll
        for (int off = 16; off; off >>= 1) v += __shfl_down_sync(0xffffffffu, v, off);
        if (t == 0) {
            int ret = atomicAdd(&g_cnt[b], v + (1 << 20));
            int tot = ret + v + (1 << 20);
            if ((tot >> 20) == CL) {
                float cfl = (float)(tot & 0xFFFFF);
                out_valid[b] = (cfl >= 16384.0f * 0.05f && cfl <= 16384.0f * 0.95f)
                               ? 1.0f : 0.0f;
            }
        }
    }
}

// ================= launch =================

extern "C" void kernel_launch(void* const* d_in, const int* in_sizes, int n_in,
                              void* d_out, int out_size) {
    const float* seg_masks   = (const float*)d_in[0];
    const float* cate_scores = (const float*)d_in[1];
    const float* feature_map = (const float*)d_in[2];
    const float* x           = (const float*)d_in[3];
    const float* targets     = (const float*)d_in[4];
    const int*   cate_labels = (const int*)d_in[5];

    float* out_scores = (float*)d_out;                  // [256]
    float* out_masks  = out_scores + NMS_N;             // [64*128*128]
    float* out_valid  = out_masks + NPIX;               // [64]

    // lazily created side stream + fork/join events (created on the first,
    // non-captured, correctness call; identical launched work every call)
    static cudaStream_t s2 = nullptr;
    static cudaEvent_t evFork = nullptr, evJoin = nullptr;
    if (s2 == nullptr) {
        cudaStreamCreateWithFlags(&s2, cudaStreamNonBlocking);
        cudaEventCreateWithFlags(&evFork, cudaEventDisableTiming);
        cudaEventCreateWithFlags(&evJoin, cudaEventDisableTiming);
    }

    // ---- fork: NMS chain on s2, CRF on the main stream ----
    cudaEventRecord(evFork, 0);
    cudaStreamWaitEvent(s2, evFork, 0);

    pack_kernel<<<NMS_N, 512, 0, s2>>>(seg_masks);
    nms_iou_kernel<<<NMS_N, NMS_N, 0, s2>>>(cate_labels);
    nms_coef_kernel<<<NMS_N, NMS_N, 0, s2>>>(cate_scores, out_scores);
    cudaEventRecord(evJoin, s2);

    crf_persistent<<<CL * NB, 1024>>>(feature_map, x, targets, out_masks, out_valid);

    // ---- join ----
    cudaStreamWaitEvent(0, evJoin, 0);
}